// round 7
// baseline (speedup 1.0000x reference)
#include <cuda_runtime.h>
#include <math.h>

#define Bb 2
#define Ss 1024
#define Dd 512
#define Hh 8
#define DKk 64
#define Rr 16
#define Gg 2
#define GDd 32
#define NHh 4
#define KMAX 64
#define KSPLIT 4
#define TI 16
#define NBLK 128

// ---------------- scratch (device globals; no allocation allowed) ----------------
__device__ float g_qtmp[KSPLIT*Bb*Ss*Hh*Rr];   // [ks][b*S+s][h*16+r]
__device__ float g_ktmp[KSPLIT*Bb*Ss*Hh*Rr];
__device__ float g_qup[Bb*Hh*Ss*DKk];
__device__ float g_kup[Bb*Hh*Ss*DKk];
__device__ unsigned g_hq[Bb*Hh*Gg*Ss];
__device__ unsigned g_hk[Bb*Hh*Gg*Ss];
__device__ unsigned g_sq[Hh*Gg*Ss];
__device__ unsigned g_sk[Hh*Gg*Ss];
__device__ int g_cand[Bb*Hh*Ss*KMAX];
__device__ int g_cnt[Bb*Hh*Ss];
__device__ int g_work[Hh*(Ss/TI)];
__device__ int g_nwork;
__device__ int g_bar_count;
__device__ int g_bar_gen;

// ---------------- software grid barrier (all NBLK blocks resident) ----------------
__device__ __forceinline__ void grid_barrier() {
    __syncthreads();
    __threadfence();                        // publish this thread's global writes
    __syncthreads();
    if (threadIdx.x == 0) {
        int gen = *(volatile int*)&g_bar_gen;
        if (atomicAdd(&g_bar_count, 1) == NBLK - 1) {
            g_bar_count = 0;
            __threadfence();
            atomicExch(&g_bar_gen, gen + 1);
        } else {
            long long spin = 0;
            while (*(volatile int*)&g_bar_gen == gen) {
                if (((++spin) & 255) == 0) __nanosleep(64);
                if (spin > (1LL << 31)) break;   // safety valve: never hang the box
            }
        }
        __threadfence();
    }
    __syncthreads();
}

// ---------------- per-phase SMEM overlays ------------------------------------------
struct GemmSmem { float As[8][128]; float Bs[8][128]; };
struct UpSmem   { float Bqs[Rr][DKk]; float Bks[Rr][DKk];
                  float qts[4][Rr]; float kts[4][Rr]; float Ps[Gg*GDd*NHh]; };
struct TrieSmem { unsigned tsign[2048]; int tj[2048];
                  unsigned rowflag[Ss/32]; unsigned flags[Ss/TI]; int fallback; };
struct SelSmem  { unsigned hks[Ss]; unsigned sks[Ss];
                  unsigned comb[TI][Ss/32]; unsigned uni[TI][Ss/32];
                  unsigned keys[Ss]; unsigned hist[256];
                  unsigned myh[TI], mys[TI]; int cnts[TI];
                  float qrow[GDd]; unsigned sDigit; int sWant; };
struct AttnSmem { float pv[Dd]; float rowv[Hh*DKk]; float q64[DKk];
                  float red[DKk]; float pp[KMAX]; int cj[KMAX]; int cnt8[Hh]; };

__global__ __launch_bounds__(256, 1)
void k_all(const float* __restrict__ query, const float* __restrict__ key,
           const float* __restrict__ value,
           const float* __restrict__ Aq, const float* __restrict__ Bq,
           const float* __restrict__ Ak, const float* __restrict__ Bk,
           const float* __restrict__ Wv, const float* __restrict__ Wo,
           const float* __restrict__ lsh, float* __restrict__ out) {
    __shared__ __align__(16) unsigned char sm[18688];
    int bid = blockIdx.x;
    int tid = threadIdx.x;

    // ================= Phase 1: dual low-rank SGEMM (one 128x128x128 tile/block) ===
    {
        GemmSmem& S = *reinterpret_cast<GemmSmem*>(sm);
        int qk = bid >> 6, ks = (bid >> 4) & 3, rowt = bid & 15;
        const float* X = qk ? key : query;
        const float* W = qk ? Ak : Aq;
        float* O = (qk ? g_ktmp : g_qtmp) + ks * (Bb*Ss) * (Hh*Rr);
        int row0 = rowt * 128;
        int d_base = ks * (Dd / KSPLIT);

        int tx = tid & 15, ty = tid >> 4;
        float acc[8][8] = {};
        int ar = tid >> 1, ac4 = (tid & 1) * 4;
        int bk = tid >> 5, bc4 = (tid & 31) * 4;

        for (int k0 = 0; k0 < Dd/KSPLIT; k0 += 8) {
            float4 av = *(const float4*)&X[(row0 + ar)*Dd + d_base + k0 + ac4];
            S.As[ac4+0][ar] = av.x; S.As[ac4+1][ar] = av.y;
            S.As[ac4+2][ar] = av.z; S.As[ac4+3][ar] = av.w;
            float4 bv = *(const float4*)&W[(bc4 >> 4)*(Dd*Rr) + (d_base + k0 + bk)*Rr + (bc4 & 15)];
            *(float4*)&S.Bs[bk][bc4] = bv;
            __syncthreads();
            #pragma unroll
            for (int kk = 0; kk < 8; ++kk) {
                float a[8], bf[8];
                *(float4*)&a[0] = *(const float4*)&S.As[kk][ty*8];
                *(float4*)&a[4] = *(const float4*)&S.As[kk][ty*8+4];
                *(float4*)&bf[0] = *(const float4*)&S.Bs[kk][tx*8];
                *(float4*)&bf[4] = *(const float4*)&S.Bs[kk][tx*8+4];
                #pragma unroll
                for (int i2 = 0; i2 < 8; ++i2)
                    #pragma unroll
                    for (int j2 = 0; j2 < 8; ++j2) acc[i2][j2] += a[i2]*bf[j2];
            }
            __syncthreads();
        }
        #pragma unroll
        for (int i2 = 0; i2 < 8; ++i2) {
            float* orow = O + (row0 + ty*8 + i2)*(Hh*Rr) + tx*8;
            *(float4*)&orow[0] = *(float4*)&acc[i2][0];
            *(float4*)&orow[4] = *(float4*)&acc[i2][4];
        }
        if (bid == 0 && tid == 0) g_nwork = 0;   // reset worklist for phase 3
    }
    grid_barrier();

    // ================= Phase 2: up-projection + LSH hash + sign pack ===============
    {
        UpSmem& S = *reinterpret_cast<UpSmem*>(sm);
        int bh = bid >> 3;                 // 16 (b,h) pairs, 8 blocks each
        int b = bh >> 3, h = bh & 7;
        int sbase = (bid & 7) * 128;       // 128 s-rows per block

        for (int t = tid; t < Rr*DKk; t += 256) {
            S.Bqs[t >> 6][t & 63] = Bq[h*Rr*DKk + t];
            S.Bks[t >> 6][t & 63] = Bk[h*Rr*DKk + t];
        }
        if (tid < Gg*GDd*NHh) S.Ps[tid] = lsh[h*(Gg*GDd*NHh) + tid];
        __syncthreads();

        int kk = tid & 63;
        int sl2 = tid >> 6;
        int g = kk >> 5;
        int d = kk & 31;

        for (int ss = 0; ss < 128; ss += 4) {
            if (tid < 128) {
                int sl = tid >> 5, r = (tid >> 1) & 15, qk = tid & 1;
                int row = b*Ss + sbase + ss + sl;
                const float* base = (qk ? g_ktmp : g_qtmp) + row*(Hh*Rr) + h*Rr + r;
                const int st = (Bb*Ss)*(Hh*Rr);
                float v = base[0] + base[st] + base[2*st] + base[3*st];
                if (qk) S.kts[sl][r] = v; else S.qts[sl][r] = v;
            }
            __syncthreads();

            int s = sbase + ss + sl2;
            float qv = 0.f, kv = 0.f;
            #pragma unroll
            for (int r = 0; r < Rr; ++r) {
                qv += S.qts[sl2][r] * S.Bqs[r][kk];
                kv += S.kts[sl2][r] * S.Bks[r][kk];
            }
            g_qup[(bh*Ss + s)*DKk + kk] = qv;
            g_kup[(bh*Ss + s)*DKk + kk] = kv;

            unsigned bq = __ballot_sync(0xffffffffu, qv > 0.f);
            unsigned bk2 = __ballot_sync(0xffffffffu, kv > 0.f);

            float hq[NHh], hk[NHh];
            #pragma unroll
            for (int n = 0; n < NHh; ++n) {
                float p = S.Ps[(g*GDd + d)*NHh + n];
                hq[n] = qv * p;
                hk[n] = kv * p;
            }
            #pragma unroll
            for (int off = 16; off >= 1; off >>= 1) {
                #pragma unroll
                for (int n = 0; n < NHh; ++n) {
                    hq[n] += __shfl_xor_sync(0xffffffffu, hq[n], off);
                    hk[n] += __shfl_xor_sync(0xffffffffu, hk[n], off);
                }
            }
            if (d == 0) {
                unsigned pq = 0u, pk = 0u;
                #pragma unroll
                for (int n = 0; n < NHh; ++n) {
                    pq |= ((unsigned)(((int)floorf(hq[n]*0.25f)) & 63)) << (8*n);
                    pk |= ((unsigned)(((int)floorf(hk[n]*0.25f)) & 63)) << (8*n);
                }
                g_hq[(bh*Gg + g)*Ss + s] = pq;
                g_hk[(bh*Gg + g)*Ss + s] = pk;
                if (b == Bb - 1) {
                    g_sq[(h*Gg + g)*Ss + s] = bq;
                    g_sk[(h*Gg + g)*Ss + s] = bk2;
                }
            }
            __syncthreads();
        }
    }
    grid_barrier();

    // ================= Phase 3: trie prefilter + worklist (blocks 0..7) ============
    if (bid < Hh) {
        TrieSmem& S = *reinterpret_cast<TrieSmem*>(sm);
        int h = bid;
        if (tid == 0) S.fallback = 0;
        for (int t = tid; t < Ss/32; t += 256) S.rowflag[t] = 0u;
        for (int g = 0; g < Gg; ++g) {
            for (int t = tid; t < 2048; t += 256) S.tj[t] = 0;
            __syncthreads();
            for (int j = tid; j < Ss; j += 256) {
                unsigned s = g_sk[(h*Gg + g)*Ss + j];
                unsigned slot = (s * 2654435761u >> 16) & 2047u;
                bool ok = false;
                for (int p = 0; p < 4096; ++p) {
                    if (atomicCAS(&S.tj[slot], 0, (int)j + 1) == 0) { S.tsign[slot] = s; ok = true; break; }
                    slot = (slot + 1) & 2047u;
                }
                if (!ok) atomicExch(&S.fallback, 1);
            }
            __syncthreads();
            for (int i = tid; i < Ss; i += 256) {
                unsigned s = g_sq[(h*Gg + g)*Ss + i];
                unsigned slot = (s * 2654435761u >> 16) & 2047u;
                bool m = true;
                for (int p = 0; p < 2048; ++p) {
                    int occ = S.tj[slot];
                    if (occ == 0) { m = false; break; }
                    if (S.tsign[slot] == s) { m = true; break; }
                    slot = (slot + 1) & 2047u;
                }
                if (m) atomicOr(&S.rowflag[i >> 5], 1u << (i & 31));
            }
            __syncthreads();
        }
        if (tid < Ss/TI) {
            unsigned w = S.rowflag[tid >> 1];
            unsigned bits = (w >> ((tid & 1) * 16)) & 0xFFFFu;
            unsigned f = (bits || S.fallback) ? 1u : 0u;
            S.flags[tid] = f;
            if (f) {
                int p = atomicAdd(&g_nwork, 1);
                g_work[p] = (h << 6) | tid;
            }
        }
        __syncthreads();
        for (int t = tid; t < Bb*Ss; t += 256) {
            int b2 = t >> 10, s = t & 1023;
            if (!S.flags[s >> 4]) g_cnt[(b2*Hh + h)*Ss + s] = 0;
        }
    }
    grid_barrier();

    // ================= Phase 4: candidate selection (worklist drain) ===============
    {
        SelSmem& S = *reinterpret_cast<SelSmem*>(sm);
        int warp = tid >> 5, lane = tid & 31;
        int nwork = g_nwork;

        for (int w = bid; w < nwork; w += NBLK) {
            int ht = g_work[w];
            int h = ht >> 6, tile = ht & 63;
            int it0 = tile * TI;
            for (int b = 0; b < Bb; ++b) {
                int bh = b*Hh + h;
                for (int t = tid; t < TI*(Ss/32); t += 256) ((unsigned*)S.uni)[t] = 0u;

                for (int g = 0; g < Gg; ++g) {
                    for (int t = tid; t < Ss; t += 256) {
                        S.hks[t] = g_hk[(bh*Gg + g)*Ss + t];
                        S.sks[t] = g_sk[(h*Gg + g)*Ss + t];
                    }
                    if (tid < TI) {
                        S.myh[tid] = g_hq[(bh*Gg + g)*Ss + it0 + tid];
                        S.mys[tid] = g_sq[(h*Gg + g)*Ss + it0 + tid];
                    }
                    __syncthreads();

                    #pragma unroll
                    for (int iw = 0; iw < 2; ++iw) {
                        int ii = warp*2 + iw;
                        unsigned mh = S.myh[ii], ms = S.mys[ii];
                        int cnt = 0;
                        for (int c = 0; c < Ss/32; ++c) {
                            int j = c*32 + lane;
                            unsigned x = mh ^ S.hks[j];
                            bool m = (((x - 0x01010101u) & ~x & 0x80808080u) != 0u) && (S.sks[j] == ms);
                            unsigned bal = __ballot_sync(0xffffffffu, m);
                            if (lane == 0) S.comb[ii][c] = bal;
                            cnt += __popc(bal);
                        }
                        if (lane == 0) S.cnts[ii] = cnt;
                    }
                    __syncthreads();

                    for (int ii = 0; ii < TI; ++ii) {
                        if (S.cnts[ii] > KMAX) {
                            if (tid < GDd) S.qrow[tid] = g_qup[(bh*Ss + it0 + ii)*DKk + g*GDd + tid];
                            __syncthreads();
                            for (int j = tid; j < Ss; j += 256) {
                                unsigned key = 0u;
                                if ((S.comb[ii][j >> 5] >> (j & 31)) & 1u) {
                                    const float* kr = g_kup + (bh*Ss + j)*DKk + g*GDd;
                                    float sd = 0.f;
                                    #pragma unroll
                                    for (int d = 0; d < GDd; ++d) sd += S.qrow[d]*kr[d];
                                    unsigned u = __float_as_uint(sd);
                                    key = (u & 0x80000000u) ? ~u : (u | 0x80000000u);
                                }
                                S.keys[j] = key;
                            }
                            __syncthreads();
                            unsigned prefix = 0u, himask = 0u;
                            int want = KMAX;
                            for (int pass = 0; pass < 4; ++pass) {
                                int shift = 24 - 8*pass;
                                S.hist[tid] = 0u;
                                __syncthreads();
                                for (int j = tid; j < Ss; j += 256) {
                                    unsigned k2 = S.keys[j];
                                    if ((k2 & himask) == prefix) atomicAdd(&S.hist[(k2 >> shift) & 255], 1u);
                                }
                                __syncthreads();
                                for (int off = 1; off < 256; off <<= 1) {
                                    unsigned add = (tid + off < 256) ? S.hist[tid + off] : 0u;
                                    __syncthreads();
                                    S.hist[tid] += add;
                                    __syncthreads();
                                }
                                unsigned sfx = S.hist[tid];
                                unsigned nxt = (tid < 255) ? S.hist[tid + 1] : 0u;
                                if (sfx >= (unsigned)want && nxt < (unsigned)want) {
                                    S.sDigit = (unsigned)tid;
                                    S.sWant = want - (int)nxt;
                                }
                                __syncthreads();
                                prefix |= S.sDigit << shift;
                                himask |= 0xFFu << shift;
                                want = S.sWant;
                                __syncthreads();
                            }
                            unsigned thresh = prefix;
                            for (int j = tid; j < Ss; j += 256)
                                if (((S.comb[ii][j >> 5] >> (j & 31)) & 1u) && S.keys[j] >= thresh)
                                    atomicOr(&S.uni[ii][j >> 5], 1u << (j & 31));
                            __syncthreads();
                        }
                    }

                    for (int t = tid; t < TI*(Ss/32); t += 256) {
                        int ii = t >> 5, w2 = t & 31;
                        if (S.cnts[ii] <= KMAX) S.uni[ii][w2] |= S.comb[ii][w2];
                    }
                    __syncthreads();
                }

                #pragma unroll
                for (int iw = 0; iw < 2; ++iw) {
                    int ii = warp*2 + iw;
                    unsigned w32 = S.uni[ii][lane];
                    int pc = __popc(w32);
                    int inc = pc;
                    #pragma unroll
                    for (int off = 1; off < 32; off <<= 1) {
                        int v = __shfl_up_sync(0xffffffffu, inc, off);
                        if (lane >= off) inc += v;
                    }
                    int pos = inc - pc;
                    int outBase = (bh*Ss + it0 + ii)*KMAX;
                    unsigned w2 = w32;
                    while (w2 && pos < KMAX) {
                        int bit = __ffs(w2) - 1;
                        w2 &= w2 - 1u;
                        g_cand[outBase + pos] = lane*32 + bit;
                        ++pos;
                    }
                    int tot = __shfl_sync(0xffffffffu, inc, 31);
                    if (lane == 0) g_cnt[bh*Ss + it0 + ii] = min(tot, KMAX);
                }
                __syncthreads();
            }
        }
    }
    grid_barrier();

    // ================= Phase 5: sparse attention + on-demand vproj + output ========
    {
        AttnSmem& S = *reinterpret_cast<AttnSmem*>(sm);
        for (int rr = 0; rr < 16; ++rr) {
            int row = bid*16 + rr;
            int b = row >> 10, i = row & 1023;
            if (tid < Hh) S.cnt8[tid] = g_cnt[(b*Hh + tid)*Ss + i];
            __syncthreads();
            int any = 0;
            #pragma unroll
            for (int h2 = 0; h2 < Hh; ++h2) any |= S.cnt8[h2];
            float* orow = out + row*Dd;
            if (!any) {
                if (tid < 128) ((float4*)orow)[tid] = make_float4(0.f, 0.f, 0.f, 0.f);
                __syncthreads();
                continue;
            }
            for (int h2 = 0; h2 < Hh; ++h2) {
                int cn = S.cnt8[h2];
                if (cn == 0) {
                    if (tid < DKk) S.rowv[h2*DKk + tid] = 0.f;
                    __syncthreads();
                    continue;
                }
                int bh = b*Hh + h2;
                if (tid < DKk) S.q64[tid] = g_qup[(bh*Ss + i)*DKk + tid];
                if (tid < cn) S.cj[tid] = g_cand[(bh*Ss + i)*KMAX + tid];
                __syncthreads();
                float s = -3.4e38f;
                if (tid < cn) {
                    const float* kr = g_kup + (bh*Ss + S.cj[tid])*DKk;
                    float acc = 0.f;
                    #pragma unroll
                    for (int d = 0; d < DKk; ++d) acc += S.q64[d]*kr[d];
                    s = acc * 0.125f;
                }
                if (tid < DKk) S.red[tid] = s;
                __syncthreads();
                for (int off = 32; off >= 1; off >>= 1) {
                    if (tid < off) S.red[tid] = fmaxf(S.red[tid], S.red[tid + off]);
                    __syncthreads();
                }
                float mx = S.red[0];
                __syncthreads();
                float e = (tid < cn) ? expf(s - mx) : 0.f;
                if (tid < DKk) S.red[tid] = e;
                __syncthreads();
                for (int off = 32; off >= 1; off >>= 1) {
                    if (tid < off) S.red[tid] += S.red[tid + off];
                    __syncthreads();
                }
                float denom = S.red[0];
                if (tid < DKk) S.pp[tid] = e / denom;
                __syncthreads();
                for (int d = tid; d < Dd; d += 256) {
                    float a = 0.f;
                    for (int c = 0; c < cn; ++c) a += S.pp[c]*value[(b*Ss + S.cj[c])*Dd + d];
                    S.pv[d] = a;
                }
                __syncthreads();
                if (tid < DKk) {
                    float a = 0.f;
                    for (int d = 0; d < Dd; ++d) a += S.pv[d]*Wv[(h2*Dd + d)*DKk + tid];
                    S.rowv[h2*DKk + tid] = a;
                }
                __syncthreads();
            }
            float a0 = 0.f, a1 = 0.f;
            for (int k2 = 0; k2 < Hh*DKk; ++k2) {
                float rv = S.rowv[k2];
                if (rv == 0.f) continue;
                a0 += rv * Wo[k2*Dd + tid];
                a1 += rv * Wo[k2*Dd + tid + 256];
            }
            orow[tid] = a0;
            orow[tid + 256] = a1;
            __syncthreads();
        }
    }
}

// ---------------- launch -----------------------------------------------------------
extern "C" void kernel_launch(void* const* d_in, const int* in_sizes, int n_in,
                              void* d_out, int out_size) {
    const float* query = (const float*)d_in[0];
    const float* key   = (const float*)d_in[1];
    const float* value = (const float*)d_in[2];
    const float* Aq    = (const float*)d_in[3];
    const float* Bq    = (const float*)d_in[4];
    const float* Ak    = (const float*)d_in[5];
    const float* Bk    = (const float*)d_in[6];
    const float* Wv    = (const float*)d_in[7];
    const float* Wo    = (const float*)d_in[8];
    const float* lsh   = (const float*)d_in[9];
    float* out = (float*)d_out;

    k_all<<<NBLK, 256>>>(query, key, value, Aq, Bq, Ak, Bk, Wv, Wo, lsh, out);
}

// round 8
// speedup vs baseline: 1.0773x; 1.0773x over previous
#include <cuda_runtime.h>
#include <math.h>

#define Bb 2
#define Ss 1024
#define Dd 512
#define Hh 8
#define DKk 64
#define Rr 16
#define Gg 2
#define GDd 32
#define NHh 4
#define KMAX 64
#define TI 16
#define NBLK3 128

// ---------------- scratch (device globals; no allocation allowed) ----------------
__device__ float g_qtmp[Bb*Ss*Hh*Rr];          // [b*S+s][h*16+r]
__device__ float g_ktmp[Bb*Ss*Hh*Rr];
__device__ float g_qup[Bb*Hh*Ss*DKk];
__device__ float g_kup[Bb*Hh*Ss*DKk];
__device__ unsigned g_hq[Bb*Hh*Gg*Ss];
__device__ unsigned g_hk[Bb*Hh*Gg*Ss];
__device__ unsigned g_sq[Hh*Gg*Ss];
__device__ unsigned g_sk[Hh*Gg*Ss];
__device__ int g_cand[Bb*Hh*Ss*KMAX];
__device__ int g_cnt[Bb*Hh*Ss];
__device__ int g_work[Hh*(Ss/TI)];
__device__ int g_nwork;
__device__ int g_bar_count;
__device__ int g_bar_gen;

__device__ __forceinline__ unsigned f2tf32(float f) {
    unsigned u;
    asm("cvt.rna.tf32.f32 %0, %1;" : "=r"(u) : "f"(f));
    return u;
}

// ---------------- K1: dual low-rank GEMM on tensor cores (tf32 mma.sync) -----------
// O[row][c] = sum_d X[row][d] * W[(c>>4)*(Dd*Rr) + d*Rr + (c&15)]
// 64 blocks: qk = bid>>5, row-tile (64 rows) = bid&31. 8 warps, warp tile 32x32.
__global__ __launch_bounds__(256)
void k_lowrank_tc(const float* __restrict__ q, const float* __restrict__ k,
                  const float* __restrict__ Aq, const float* __restrict__ Ak) {
    __shared__ unsigned As[32][68];    // [k][m] tf32 bits (pad 4 -> conflict-free frags)
    __shared__ unsigned Bs[32][132];   // [k][n]
    int bid = blockIdx.x;
    int qk = bid >> 5, rowt = bid & 31;
    const float* X = qk ? k : q;
    const float* W = qk ? Ak : Aq;
    float* O = qk ? g_ktmp : g_qtmp;
    int row0 = rowt * 64;
    int tid = threadIdx.x;
    int warp = tid >> 5, lane = tid & 31;
    int gid = lane >> 2, tig = lane & 3;
    int wr = warp >> 2, wc = warp & 3;        // warp tile origin (wr*32, wc*32)
    float acc[2][4][4] = {};

    for (int kb = 0; kb < Dd; kb += 32) {
        // A: 64 rows x 32 k  (512 float4 loads, 2/thread), transpose into As[k][m]
        #pragma unroll
        for (int i = 0; i < 2; ++i) {
            int idx = tid*2 + i;
            int m = idx >> 3, k4 = (idx & 7) * 4;
            float4 v = *(const float4*)&X[(row0 + m)*Dd + kb + k4];
            As[k4+0][m] = f2tf32(v.x);
            As[k4+1][m] = f2tf32(v.y);
            As[k4+2][m] = f2tf32(v.z);
            As[k4+3][m] = f2tf32(v.w);
        }
        // B: 32 k x 128 n  (1024 float4 loads, 4/thread) into Bs[k][n]
        #pragma unroll
        for (int i = 0; i < 4; ++i) {
            int idx = tid*4 + i;
            int kk = idx >> 5, n4 = (idx & 31) * 4;   // n4 aligned within 16-col head slice
            const float* src = &W[(n4 >> 4)*(Dd*Rr) + (kb + kk)*Rr + (n4 & 15)];
            float4 v = *(const float4*)src;
            Bs[kk][n4+0] = f2tf32(v.x);
            Bs[kk][n4+1] = f2tf32(v.y);
            Bs[kk][n4+2] = f2tf32(v.z);
            Bs[kk][n4+3] = f2tf32(v.w);
        }
        __syncthreads();
        #pragma unroll
        for (int ks = 0; ks < 4; ++ks) {
            int k0 = ks * 8;
            unsigned a[2][4], b[4][2];
            #pragma unroll
            for (int mt = 0; mt < 2; ++mt) {
                int m0 = wr*32 + mt*16;
                a[mt][0] = As[k0+tig  ][m0+gid  ];
                a[mt][1] = As[k0+tig  ][m0+gid+8];
                a[mt][2] = As[k0+tig+4][m0+gid  ];
                a[mt][3] = As[k0+tig+4][m0+gid+8];
            }
            #pragma unroll
            for (int nt = 0; nt < 4; ++nt) {
                int n0 = wc*32 + nt*8;
                b[nt][0] = Bs[k0+tig  ][n0+gid];
                b[nt][1] = Bs[k0+tig+4][n0+gid];
            }
            #pragma unroll
            for (int mt = 0; mt < 2; ++mt)
                #pragma unroll
                for (int nt = 0; nt < 4; ++nt) {
                    float* c = acc[mt][nt];
                    asm volatile(
                        "mma.sync.aligned.m16n8k8.row.col.f32.tf32.tf32.f32 "
                        "{%0,%1,%2,%3}, {%4,%5,%6,%7}, {%8,%9}, {%0,%1,%2,%3};"
                        : "+f"(c[0]), "+f"(c[1]), "+f"(c[2]), "+f"(c[3])
                        : "r"(a[mt][0]), "r"(a[mt][1]), "r"(a[mt][2]), "r"(a[mt][3]),
                          "r"(b[nt][0]), "r"(b[nt][1]));
                }
        }
        __syncthreads();
    }
    #pragma unroll
    for (int mt = 0; mt < 2; ++mt)
        #pragma unroll
        for (int nt = 0; nt < 4; ++nt) {
            int m0 = row0 + wr*32 + mt*16, n0 = wc*32 + nt*8;
            O[(m0+gid  )*(Hh*Rr) + n0 + 2*tig  ] = acc[mt][nt][0];
            O[(m0+gid  )*(Hh*Rr) + n0 + 2*tig+1] = acc[mt][nt][1];
            O[(m0+gid+8)*(Hh*Rr) + n0 + 2*tig  ] = acc[mt][nt][2];
            O[(m0+gid+8)*(Hh*Rr) + n0 + 2*tig+1] = acc[mt][nt][3];
        }
}

// ---------------- K2: fused up-projection + LSH hash + sign pack (16 s/block) ------
__global__ void k_upproj_hash(const float* __restrict__ Bq, const float* __restrict__ Bk,
                              const float* __restrict__ lsh) {
    __shared__ float Bqs[Rr][DKk];
    __shared__ float Bks[Rr][DKk];
    __shared__ float qts[4][Rr];
    __shared__ float kts[4][Rr];
    __shared__ float Ps[Gg*GDd*NHh];

    int blk = blockIdx.x;
    int s0 = (blk % (Ss/16)) * 16;
    int h = (blk / (Ss/16)) % Hh;
    int b = blk / ((Ss/16) * Hh);
    int tid = threadIdx.x;

    if (blk == 0 && tid == 0) g_nwork = 0;     // reset worklist for K3
    for (int t = tid; t < Rr*DKk; t += 256) {
        Bqs[t >> 6][t & 63] = Bq[h*Rr*DKk + t];
        Bks[t >> 6][t & 63] = Bk[h*Rr*DKk + t];
    }
    if (tid < Gg*GDd*NHh) Ps[tid] = lsh[h*(Gg*GDd*NHh) + tid];

    int kk = tid & 63;
    int sl2 = tid >> 6;
    int g = kk >> 5;
    int d = kk & 31;
    int bh = b*Hh + h;

    for (int ss = 0; ss < 16; ss += 4) {
        if (tid < 128) {
            int sl = tid >> 5, r = (tid >> 1) & 15, qk = tid & 1;
            int row = b*Ss + s0 + ss + sl;
            float v = (qk ? g_ktmp : g_qtmp)[row*(Hh*Rr) + h*Rr + r];
            if (qk) kts[sl][r] = v; else qts[sl][r] = v;
        }
        __syncthreads();

        int s = s0 + ss + sl2;
        float qv = 0.f, kv = 0.f;
        #pragma unroll
        for (int r = 0; r < Rr; ++r) {
            qv += qts[sl2][r] * Bqs[r][kk];
            kv += kts[sl2][r] * Bks[r][kk];
        }
        g_qup[(bh*Ss + s)*DKk + kk] = qv;
        g_kup[(bh*Ss + s)*DKk + kk] = kv;

        unsigned bq = __ballot_sync(0xffffffffu, qv > 0.f);
        unsigned bk2 = __ballot_sync(0xffffffffu, kv > 0.f);

        float hq[NHh], hk[NHh];
        #pragma unroll
        for (int n = 0; n < NHh; ++n) {
            float p = Ps[(g*GDd + d)*NHh + n];
            hq[n] = qv * p;
            hk[n] = kv * p;
        }
        #pragma unroll
        for (int off = 16; off >= 1; off >>= 1) {
            #pragma unroll
            for (int n = 0; n < NHh; ++n) {
                hq[n] += __shfl_xor_sync(0xffffffffu, hq[n], off);
                hk[n] += __shfl_xor_sync(0xffffffffu, hk[n], off);
            }
        }
        if (d == 0) {
            unsigned pq = 0u, pk = 0u;
            #pragma unroll
            for (int n = 0; n < NHh; ++n) {
                pq |= ((unsigned)(((int)floorf(hq[n]*0.25f)) & 63)) << (8*n);
                pk |= ((unsigned)(((int)floorf(hk[n]*0.25f)) & 63)) << (8*n);
            }
            g_hq[(bh*Gg + g)*Ss + s] = pq;
            g_hk[(bh*Gg + g)*Ss + s] = pk;
            if (b == Bb - 1) {
                g_sq[(h*Gg + g)*Ss + s] = bq;
                g_sk[(h*Gg + g)*Ss + s] = bk2;
            }
        }
        __syncthreads();
    }
}

// ---------------- K3: persistent trie + select + attn_out (128 blocks) -------------
__device__ __forceinline__ void grid_barrier3() {
    __syncthreads();
    __threadfence();
    __syncthreads();
    if (threadIdx.x == 0) {
        int gen = *(volatile int*)&g_bar_gen;
        if (atomicAdd(&g_bar_count, 1) == NBLK3 - 1) {
            g_bar_count = 0;
            __threadfence();
            atomicExch(&g_bar_gen, gen + 1);
        } else {
            long long spin = 0;
            while (*(volatile int*)&g_bar_gen == gen) {
                if (((++spin) & 255) == 0) __nanosleep(64);
                if (spin > (1LL << 31)) break;   // safety valve: never hang the box
            }
        }
        __threadfence();
    }
    __syncthreads();
}

struct TrieSmem { unsigned tsign[2048]; int tj[2048];
                  unsigned rowflag[Ss/32]; unsigned flags[Ss/TI]; int fallback; };
struct SelSmem  { unsigned hks[Ss]; unsigned sks[Ss];
                  unsigned comb[TI][Ss/32]; unsigned uni[TI][Ss/32];
                  unsigned keys[Ss]; unsigned hist[256];
                  unsigned myh[TI], mys[TI]; int cnts[TI];
                  float qrow[GDd]; unsigned sDigit; int sWant; };
struct AttnSmem { float pv[Dd]; float rowv[Hh*DKk]; float q64[DKk];
                  float red[DKk]; float pp[KMAX]; int cj[KMAX]; int cnt8[Hh]; };

__global__ __launch_bounds__(256, 1)
void k_tail(const float* __restrict__ value, const float* __restrict__ Wv,
            const float* __restrict__ Wo, float* __restrict__ out) {
    __shared__ __align__(16) unsigned char sm[18688];
    int bid = blockIdx.x;
    int tid = threadIdx.x;

    // ===== Phase A: trie prefilter + worklist (blocks 0..7) =====
    if (bid < Hh) {
        TrieSmem& S = *reinterpret_cast<TrieSmem*>(sm);
        int h = bid;
        if (tid == 0) S.fallback = 0;
        for (int t = tid; t < Ss/32; t += 256) S.rowflag[t] = 0u;
        for (int g = 0; g < Gg; ++g) {
            for (int t = tid; t < 2048; t += 256) S.tj[t] = 0;
            __syncthreads();
            for (int j = tid; j < Ss; j += 256) {
                unsigned s = g_sk[(h*Gg + g)*Ss + j];
                unsigned slot = (s * 2654435761u >> 16) & 2047u;
                bool ok = false;
                for (int p = 0; p < 4096; ++p) {
                    if (atomicCAS(&S.tj[slot], 0, (int)j + 1) == 0) { S.tsign[slot] = s; ok = true; break; }
                    slot = (slot + 1) & 2047u;
                }
                if (!ok) atomicExch(&S.fallback, 1);
            }
            __syncthreads();
            for (int i = tid; i < Ss; i += 256) {
                unsigned s = g_sq[(h*Gg + g)*Ss + i];
                unsigned slot = (s * 2654435761u >> 16) & 2047u;
                bool m = true;
                for (int p = 0; p < 2048; ++p) {
                    int occ = S.tj[slot];
                    if (occ == 0) { m = false; break; }
                    if (S.tsign[slot] == s) { m = true; break; }
                    slot = (slot + 1) & 2047u;
                }
                if (m) atomicOr(&S.rowflag[i >> 5], 1u << (i & 31));
            }
            __syncthreads();
        }
        if (tid < Ss/TI) {
            unsigned w = S.rowflag[tid >> 1];
            unsigned bits = (w >> ((tid & 1) * 16)) & 0xFFFFu;
            unsigned f = (bits || S.fallback) ? 1u : 0u;
            S.flags[tid] = f;
            if (f) {
                int p = atomicAdd(&g_nwork, 1);
                g_work[p] = (h << 6) | tid;
            }
        }
        __syncthreads();
        for (int t = tid; t < Bb*Ss; t += 256) {
            int b2 = t >> 10, s = t & 1023;
            if (!S.flags[s >> 4]) g_cnt[(b2*Hh + h)*Ss + s] = 0;
        }
    }
    grid_barrier3();

    // ===== Phase B: candidate selection (worklist drain) =====
    {
        SelSmem& S = *reinterpret_cast<SelSmem*>(sm);
        int warp = tid >> 5, lane = tid & 31;
        int nwork = g_nwork;

        for (int w = bid; w < nwork; w += NBLK3) {
            int ht = g_work[w];
            int h = ht >> 6, tile = ht & 63;
            int it0 = tile * TI;
            for (int b = 0; b < Bb; ++b) {
                int bh = b*Hh + h;
                for (int t = tid; t < TI*(Ss/32); t += 256) ((unsigned*)S.uni)[t] = 0u;

                for (int g = 0; g < Gg; ++g) {
                    for (int t = tid; t < Ss; t += 256) {
                        S.hks[t] = g_hk[(bh*Gg + g)*Ss + t];
                        S.sks[t] = g_sk[(h*Gg + g)*Ss + t];
                    }
                    if (tid < TI) {
                        S.myh[tid] = g_hq[(bh*Gg + g)*Ss + it0 + tid];
                        S.mys[tid] = g_sq[(h*Gg + g)*Ss + it0 + tid];
                    }
                    __syncthreads();

                    #pragma unroll
                    for (int iw = 0; iw < 2; ++iw) {
                        int ii = warp*2 + iw;
                        unsigned mh = S.myh[ii], ms = S.mys[ii];
                        int cnt = 0;
                        for (int c = 0; c < Ss/32; ++c) {
                            int j = c*32 + lane;
                            unsigned x = mh ^ S.hks[j];
                            bool m = (((x - 0x01010101u) & ~x & 0x80808080u) != 0u) && (S.sks[j] == ms);
                            unsigned bal = __ballot_sync(0xffffffffu, m);
                            if (lane == 0) S.comb[ii][c] = bal;
                            cnt += __popc(bal);
                        }
                        if (lane == 0) S.cnts[ii] = cnt;
                    }
                    __syncthreads();

                    for (int ii = 0; ii < TI; ++ii) {
                        if (S.cnts[ii] > KMAX) {
                            if (tid < GDd) S.qrow[tid] = g_qup[(bh*Ss + it0 + ii)*DKk + g*GDd + tid];
                            __syncthreads();
                            for (int j = tid; j < Ss; j += 256) {
                                unsigned key = 0u;
                                if ((S.comb[ii][j >> 5] >> (j & 31)) & 1u) {
                                    const float* kr = g_kup + (bh*Ss + j)*DKk + g*GDd;
                                    float sd = 0.f;
                                    #pragma unroll
                                    for (int d = 0; d < GDd; ++d) sd += S.qrow[d]*kr[d];
                                    unsigned u = __float_as_uint(sd);
                                    key = (u & 0x80000000u) ? ~u : (u | 0x80000000u);
                                }
                                S.keys[j] = key;
                            }
                            __syncthreads();
                            unsigned prefix = 0u, himask = 0u;
                            int want = KMAX;
                            for (int pass = 0; pass < 4; ++pass) {
                                int shift = 24 - 8*pass;
                                S.hist[tid] = 0u;
                                __syncthreads();
                                for (int j = tid; j < Ss; j += 256) {
                                    unsigned k2 = S.keys[j];
                                    if ((k2 & himask) == prefix) atomicAdd(&S.hist[(k2 >> shift) & 255], 1u);
                                }
                                __syncthreads();
                                for (int off = 1; off < 256; off <<= 1) {
                                    unsigned add = (tid + off < 256) ? S.hist[tid + off] : 0u;
                                    __syncthreads();
                                    S.hist[tid] += add;
                                    __syncthreads();
                                }
                                unsigned sfx = S.hist[tid];
                                unsigned nxt = (tid < 255) ? S.hist[tid + 1] : 0u;
                                if (sfx >= (unsigned)want && nxt < (unsigned)want) {
                                    S.sDigit = (unsigned)tid;
                                    S.sWant = want - (int)nxt;
                                }
                                __syncthreads();
                                prefix |= S.sDigit << shift;
                                himask |= 0xFFu << shift;
                                want = S.sWant;
                                __syncthreads();
                            }
                            unsigned thresh = prefix;
                            for (int j = tid; j < Ss; j += 256)
                                if (((S.comb[ii][j >> 5] >> (j & 31)) & 1u) && S.keys[j] >= thresh)
                                    atomicOr(&S.uni[ii][j >> 5], 1u << (j & 31));
                            __syncthreads();
                        }
                    }

                    for (int t = tid; t < TI*(Ss/32); t += 256) {
                        int ii = t >> 5, w2 = t & 31;
                        if (S.cnts[ii] <= KMAX) S.uni[ii][w2] |= S.comb[ii][w2];
                    }
                    __syncthreads();
                }

                #pragma unroll
                for (int iw = 0; iw < 2; ++iw) {
                    int ii = warp*2 + iw;
                    unsigned w32 = S.uni[ii][lane];
                    int pc = __popc(w32);
                    int inc = pc;
                    #pragma unroll
                    for (int off = 1; off < 32; off <<= 1) {
                        int v = __shfl_up_sync(0xffffffffu, inc, off);
                        if (lane >= off) inc += v;
                    }
                    int pos = inc - pc;
                    int outBase = (bh*Ss + it0 + ii)*KMAX;
                    unsigned w2 = w32;
                    while (w2 && pos < KMAX) {
                        int bit = __ffs(w2) - 1;
                        w2 &= w2 - 1u;
                        g_cand[outBase + pos] = lane*32 + bit;
                        ++pos;
                    }
                    int tot = __shfl_sync(0xffffffffu, inc, 31);
                    if (lane == 0) g_cnt[bh*Ss + it0 + ii] = min(tot, KMAX);
                }
                __syncthreads();
            }
        }
    }
    grid_barrier3();

    // ===== Phase C: sparse attention + on-demand vproj + output GEMM =====
    {
        AttnSmem& S = *reinterpret_cast<AttnSmem*>(sm);
        for (int rr = 0; rr < 16; ++rr) {
            int row = bid*16 + rr;
            int b = row >> 10, i = row & 1023;
            if (tid < Hh) S.cnt8[tid] = g_cnt[(b*Hh + tid)*Ss + i];
            __syncthreads();
            int any = 0;
            #pragma unroll
            for (int h2 = 0; h2 < Hh; ++h2) any |= S.cnt8[h2];
            float* orow = out + row*Dd;
            if (!any) {
                if (tid < 128) ((float4*)orow)[tid] = make_float4(0.f, 0.f, 0.f, 0.f);
                __syncthreads();
                continue;
            }
            for (int h2 = 0; h2 < Hh; ++h2) {
                int cn = S.cnt8[h2];
                if (cn == 0) {
                    if (tid < DKk) S.rowv[h2*DKk + tid] = 0.f;
                    __syncthreads();
                    continue;
                }
                int bh = b*Hh + h2;
                if (tid < DKk) S.q64[tid] = g_qup[(bh*Ss + i)*DKk + tid];
                if (tid < cn) S.cj[tid] = g_cand[(bh*Ss + i)*KMAX + tid];
                __syncthreads();
                float s = -3.4e38f;
                if (tid < cn) {
                    const float* kr = g_kup + (bh*Ss + S.cj[tid])*DKk;
                    float acc = 0.f;
                    #pragma unroll
                    for (int d = 0; d < DKk; ++d) acc += S.q64[d]*kr[d];
                    s = acc * 0.125f;
                }
                if (tid < DKk) S.red[tid] = s;
                __syncthreads();
                for (int off = 32; off >= 1; off >>= 1) {
                    if (tid < off) S.red[tid] = fmaxf(S.red[tid], S.red[tid + off]);
                    __syncthreads();
                }
                float mx = S.red[0];
                __syncthreads();
                float e = (tid < cn) ? expf(s - mx) : 0.f;
                if (tid < DKk) S.red[tid] = e;
                __syncthreads();
                for (int off = 32; off >= 1; off >>= 1) {
                    if (tid < off) S.red[tid] += S.red[tid + off];
                    __syncthreads();
                }
                float denom = S.red[0];
                if (tid < DKk) S.pp[tid] = e / denom;
                __syncthreads();
                for (int d = tid; d < Dd; d += 256) {
                    float a = 0.f;
                    for (int c = 0; c < cn; ++c) a += S.pp[c]*value[(b*Ss + S.cj[c])*Dd + d];
                    S.pv[d] = a;
                }
                __syncthreads();
                if (tid < DKk) {
                    float a = 0.f;
                    for (int d = 0; d < Dd; ++d) a += S.pv[d]*Wv[(h2*Dd + d)*DKk + tid];
                    S.rowv[h2*DKk + tid] = a;
                }
                __syncthreads();
            }
            float a0 = 0.f, a1 = 0.f;
            for (int k2 = 0; k2 < Hh*DKk; ++k2) {
                float rv = S.rowv[k2];
                if (rv == 0.f) continue;
                a0 += rv * Wo[k2*Dd + tid];
                a1 += rv * Wo[k2*Dd + tid + 256];
            }
            orow[tid] = a0;
            orow[tid + 256] = a1;
            __syncthreads();
        }
    }
}

// ---------------- launch -----------------------------------------------------------
extern "C" void kernel_launch(void* const* d_in, const int* in_sizes, int n_in,
                              void* d_out, int out_size) {
    const float* query = (const float*)d_in[0];
    const float* key   = (const float*)d_in[1];
    const float* value = (const float*)d_in[2];
    const float* Aq    = (const float*)d_in[3];
    const float* Bq    = (const float*)d_in[4];
    const float* Ak    = (const float*)d_in[5];
    const float* Bk    = (const float*)d_in[6];
    const float* Wv    = (const float*)d_in[7];
    const float* Wo    = (const float*)d_in[8];
    const float* lsh   = (const float*)d_in[9];
    float* out = (float*)d_out;

    k_lowrank_tc<<<64, 256>>>(query, key, Aq, Ak);
    k_upproj_hash<<<Bb*Hh*(Ss/16), 256>>>(Bq, Bk, lsh);
    k_tail<<<NBLK3, 256>>>(value, Wv, Wo, out);
}

// round 9
// speedup vs baseline: 1.3103x; 1.2163x over previous
#include <cuda_runtime.h>
#include <math.h>

#define Bb 2
#define Ss 1024
#define Dd 512
#define Hh 8
#define DKk 64
#define Rr 16
#define Gg 2
#define GDd 32
#define NHh 4
#define KMAX 64
#define KSPLIT 4
#define TI 16
#define NBLK3 128

// ---------------- scratch (device globals; no allocation allowed) ----------------
__device__ float g_qtmp[KSPLIT*Bb*Ss*Hh*Rr];   // [ks][b*S+s][h*16+r]
__device__ float g_ktmp[KSPLIT*Bb*Ss*Hh*Rr];
__device__ float g_qup[Bb*Hh*Ss*DKk];
__device__ float g_kup[Bb*Hh*Ss*DKk];
__device__ unsigned g_hq[Bb*Hh*Gg*Ss];
__device__ unsigned g_hk[Bb*Hh*Gg*Ss];
__device__ unsigned g_sq[Hh*Gg*Ss];
__device__ unsigned g_sk[Hh*Gg*Ss];
__device__ int g_cand[Bb*Hh*Ss*KMAX];
__device__ int g_cnt[Bb*Hh*Ss];
__device__ int g_work[Hh*(Ss/TI)];
__device__ int g_nwork;
__device__ int g_bar_count;
__device__ int g_bar_gen;

__device__ __forceinline__ unsigned f2tf32(float f) {
    unsigned u;
    asm("cvt.rna.tf32.f32 %0, %1;" : "=r"(u) : "f"(f));
    return u;
}

// ---------------- K1: dual low-rank GEMM, tf32 mma.sync, 4-way K-split -------------
// partial O[ks][row][c] = sum_{d in 128-chunk ks} X[row][d] * W[(c>>4)*(Dd*Rr)+d*Rr+(c&15)]
// grid (32 rowtiles, 4 ksplits, 2 qk) = 256 blocks; 8 warps; warp tile 32x32.
__global__ __launch_bounds__(256)
void k_lowrank_tc(const float* __restrict__ q, const float* __restrict__ k,
                  const float* __restrict__ Aq, const float* __restrict__ Ak) {
    __shared__ unsigned As[32][68];    // [k][m] tf32 bits
    __shared__ unsigned Bs[32][132];   // [k][n]
    int rowt = blockIdx.x, ks = blockIdx.y, qk = blockIdx.z;
    const float* X = qk ? k : q;
    const float* W = qk ? Ak : Aq;
    float* O = (qk ? g_ktmp : g_qtmp) + ks * (Bb*Ss) * (Hh*Rr);
    int row0 = rowt * 64;
    int d_base = ks * (Dd / KSPLIT);
    int tid = threadIdx.x;
    int warp = tid >> 5, lane = tid & 31;
    int gid = lane >> 2, tig = lane & 3;
    int wr = warp >> 2, wc = warp & 3;        // warp tile origin (wr*32, wc*32)
    float acc[2][4][4] = {};

    for (int kb = 0; kb < Dd/KSPLIT; kb += 32) {
        #pragma unroll
        for (int i = 0; i < 2; ++i) {
            int idx = tid*2 + i;
            int m = idx >> 3, k4 = (idx & 7) * 4;
            float4 v = *(const float4*)&X[(row0 + m)*Dd + d_base + kb + k4];
            As[k4+0][m] = f2tf32(v.x);
            As[k4+1][m] = f2tf32(v.y);
            As[k4+2][m] = f2tf32(v.z);
            As[k4+3][m] = f2tf32(v.w);
        }
        #pragma unroll
        for (int i = 0; i < 4; ++i) {
            int idx = tid*4 + i;
            int kk = idx >> 5, n4 = (idx & 31) * 4;
            const float* src = &W[(n4 >> 4)*(Dd*Rr) + (d_base + kb + kk)*Rr + (n4 & 15)];
            float4 v = *(const float4*)src;
            Bs[kk][n4+0] = f2tf32(v.x);
            Bs[kk][n4+1] = f2tf32(v.y);
            Bs[kk][n4+2] = f2tf32(v.z);
            Bs[kk][n4+3] = f2tf32(v.w);
        }
        __syncthreads();
        #pragma unroll
        for (int kks = 0; kks < 4; ++kks) {
            int k0 = kks * 8;
            unsigned a[2][4], b[4][2];
            #pragma unroll
            for (int mt = 0; mt < 2; ++mt) {
                int m0 = wr*32 + mt*16;
                a[mt][0] = As[k0+tig  ][m0+gid  ];
                a[mt][1] = As[k0+tig  ][m0+gid+8];
                a[mt][2] = As[k0+tig+4][m0+gid  ];
                a[mt][3] = As[k0+tig+4][m0+gid+8];
            }
            #pragma unroll
            for (int nt = 0; nt < 4; ++nt) {
                int n0 = wc*32 + nt*8;
                b[nt][0] = Bs[k0+tig  ][n0+gid];
                b[nt][1] = Bs[k0+tig+4][n0+gid];
            }
            #pragma unroll
            for (int mt = 0; mt < 2; ++mt)
                #pragma unroll
                for (int nt = 0; nt < 4; ++nt) {
                    float* c = acc[mt][nt];
                    asm volatile(
                        "mma.sync.aligned.m16n8k8.row.col.f32.tf32.tf32.f32 "
                        "{%0,%1,%2,%3}, {%4,%5,%6,%7}, {%8,%9}, {%0,%1,%2,%3};"
                        : "+f"(c[0]), "+f"(c[1]), "+f"(c[2]), "+f"(c[3])
                        : "r"(a[mt][0]), "r"(a[mt][1]), "r"(a[mt][2]), "r"(a[mt][3]),
                          "r"(b[nt][0]), "r"(b[nt][1]));
                }
        }
        __syncthreads();
    }
    #pragma unroll
    for (int mt = 0; mt < 2; ++mt)
        #pragma unroll
        for (int nt = 0; nt < 4; ++nt) {
            int m0 = row0 + wr*32 + mt*16, n0 = wc*32 + nt*8;
            O[(m0+gid  )*(Hh*Rr) + n0 + 2*tig  ] = acc[mt][nt][0];
            O[(m0+gid  )*(Hh*Rr) + n0 + 2*tig+1] = acc[mt][nt][1];
            O[(m0+gid+8)*(Hh*Rr) + n0 + 2*tig  ] = acc[mt][nt][2];
            O[(m0+gid+8)*(Hh*Rr) + n0 + 2*tig+1] = acc[mt][nt][3];
        }
}

// ---------------- K2: fused up-projection + LSH hash + sign pack (16 s/block) ------
__global__ void k_upproj_hash(const float* __restrict__ Bq, const float* __restrict__ Bk,
                              const float* __restrict__ lsh) {
    __shared__ float Bqs[Rr][DKk];
    __shared__ float Bks[Rr][DKk];
    __shared__ float qts[4][Rr];
    __shared__ float kts[4][Rr];
    __shared__ float Ps[Gg*GDd*NHh];

    int blk = blockIdx.x;
    int s0 = (blk % (Ss/16)) * 16;
    int h = (blk / (Ss/16)) % Hh;
    int b = blk / ((Ss/16) * Hh);
    int tid = threadIdx.x;

    if (blk == 0 && tid == 0) g_nwork = 0;     // reset worklist for K3
    for (int t = tid; t < Rr*DKk; t += 256) {
        Bqs[t >> 6][t & 63] = Bq[h*Rr*DKk + t];
        Bks[t >> 6][t & 63] = Bk[h*Rr*DKk + t];
    }
    if (tid < Gg*GDd*NHh) Ps[tid] = lsh[h*(Gg*GDd*NHh) + tid];

    int kk = tid & 63;
    int sl2 = tid >> 6;
    int g = kk >> 5;
    int d = kk & 31;
    int bh = b*Hh + h;

    for (int ss = 0; ss < 16; ss += 4) {
        if (tid < 128) {
            int sl = tid >> 5, r = (tid >> 1) & 15, qk = tid & 1;
            int row = b*Ss + s0 + ss + sl;
            const float* base = (qk ? g_ktmp : g_qtmp) + row*(Hh*Rr) + h*Rr + r;
            const int st = (Bb*Ss)*(Hh*Rr);
            float v = base[0] + base[st] + base[2*st] + base[3*st];
            if (qk) kts[sl][r] = v; else qts[sl][r] = v;
        }
        __syncthreads();

        int s = s0 + ss + sl2;
        float qv = 0.f, kv = 0.f;
        #pragma unroll
        for (int r = 0; r < Rr; ++r) {
            qv += qts[sl2][r] * Bqs[r][kk];
            kv += kts[sl2][r] * Bks[r][kk];
        }
        g_qup[(bh*Ss + s)*DKk + kk] = qv;
        g_kup[(bh*Ss + s)*DKk + kk] = kv;

        unsigned bq = __ballot_sync(0xffffffffu, qv > 0.f);
        unsigned bk2 = __ballot_sync(0xffffffffu, kv > 0.f);

        float hq[NHh], hk[NHh];
        #pragma unroll
        for (int n = 0; n < NHh; ++n) {
            float p = Ps[(g*GDd + d)*NHh + n];
            hq[n] = qv * p;
            hk[n] = kv * p;
        }
        #pragma unroll
        for (int off = 16; off >= 1; off >>= 1) {
            #pragma unroll
            for (int n = 0; n < NHh; ++n) {
                hq[n] += __shfl_xor_sync(0xffffffffu, hq[n], off);
                hk[n] += __shfl_xor_sync(0xffffffffu, hk[n], off);
            }
        }
        if (d == 0) {
            unsigned pq = 0u, pk = 0u;
            #pragma unroll
            for (int n = 0; n < NHh; ++n) {
                pq |= ((unsigned)(((int)floorf(hq[n]*0.25f)) & 63)) << (8*n);
                pk |= ((unsigned)(((int)floorf(hk[n]*0.25f)) & 63)) << (8*n);
            }
            g_hq[(bh*Gg + g)*Ss + s] = pq;
            g_hk[(bh*Gg + g)*Ss + s] = pk;
            if (b == Bb - 1) {
                g_sq[(h*Gg + g)*Ss + s] = bq;
                g_sk[(h*Gg + g)*Ss + s] = bk2;
            }
        }
        __syncthreads();
    }
}

// ---------------- K3: persistent trie + select + attn_out (128 blocks) -------------
__device__ __forceinline__ void grid_barrier3() {
    __syncthreads();
    __threadfence();
    __syncthreads();
    if (threadIdx.x == 0) {
        int gen = *(volatile int*)&g_bar_gen;
        if (atomicAdd(&g_bar_count, 1) == NBLK3 - 1) {
            g_bar_count = 0;
            __threadfence();
            atomicExch(&g_bar_gen, gen + 1);
        } else {
            long long spin = 0;
            while (*(volatile int*)&g_bar_gen == gen) {
                if (((++spin) & 255) == 0) __nanosleep(64);
                if (spin > (1LL << 31)) break;   // safety valve: never hang the box
            }
        }
        __threadfence();
    }
    __syncthreads();
}

struct TrieSmem { unsigned tsign[2048]; int tj[2048];
                  unsigned rowflag[Ss/32]; unsigned flags[Ss/TI]; int fallback; };
struct SelSmem  { unsigned hks[Ss]; unsigned sks[Ss];
                  unsigned comb[TI][Ss/32]; unsigned uni[TI][Ss/32];
                  unsigned keys[Ss]; unsigned hist[256];
                  unsigned myh[TI], mys[TI]; int cnts[TI];
                  float qrow[GDd]; unsigned sDigit; int sWant; };
struct AttnSmem { float pv[Dd]; float rowv[Hh*DKk]; float q64[DKk];
                  float red[DKk]; float pp[KMAX]; int cj[KMAX]; int cnt8[Hh]; };

__global__ __launch_bounds__(256, 1)
void k_tail(const float* __restrict__ value, const float* __restrict__ Wv,
            const float* __restrict__ Wo, float* __restrict__ out) {
    __shared__ __align__(16) unsigned char sm[18688];
    int bid = blockIdx.x;
    int tid = threadIdx.x;

    // ===== Phase A: trie prefilter + worklist (blocks 0..7) =====
    if (bid < Hh) {
        TrieSmem& S = *reinterpret_cast<TrieSmem*>(sm);
        int h = bid;
        if (tid == 0) S.fallback = 0;
        for (int t = tid; t < Ss/32; t += 256) S.rowflag[t] = 0u;
        for (int g = 0; g < Gg; ++g) {
            for (int t = tid; t < 2048; t += 256) S.tj[t] = 0;
            __syncthreads();
            for (int j = tid; j < Ss; j += 256) {
                unsigned s = g_sk[(h*Gg + g)*Ss + j];
                unsigned slot = (s * 2654435761u >> 16) & 2047u;
                bool ok = false;
                for (int p = 0; p < 4096; ++p) {
                    if (atomicCAS(&S.tj[slot], 0, (int)j + 1) == 0) { S.tsign[slot] = s; ok = true; break; }
                    slot = (slot + 1) & 2047u;
                }
                if (!ok) atomicExch(&S.fallback, 1);
            }
            __syncthreads();
            for (int i = tid; i < Ss; i += 256) {
                unsigned s = g_sq[(h*Gg + g)*Ss + i];
                unsigned slot = (s * 2654435761u >> 16) & 2047u;
                bool m = true;
                for (int p = 0; p < 2048; ++p) {
                    int occ = S.tj[slot];
                    if (occ == 0) { m = false; break; }
                    if (S.tsign[slot] == s) { m = true; break; }
                    slot = (slot + 1) & 2047u;
                }
                if (m) atomicOr(&S.rowflag[i >> 5], 1u << (i & 31));
            }
            __syncthreads();
        }
        if (tid < Ss/TI) {
            unsigned w = S.rowflag[tid >> 1];
            unsigned bits = (w >> ((tid & 1) * 16)) & 0xFFFFu;
            unsigned f = (bits || S.fallback) ? 1u : 0u;
            S.flags[tid] = f;
            if (f) {
                int p = atomicAdd(&g_nwork, 1);
                g_work[p] = (h << 6) | tid;
            }
        }
        __syncthreads();
        for (int t = tid; t < Bb*Ss; t += 256) {
            int b2 = t >> 10, s = t & 1023;
            if (!S.flags[s >> 4]) g_cnt[(b2*Hh + h)*Ss + s] = 0;
        }
    }
    grid_barrier3();

    // ===== Phase B: candidate selection (worklist drain) =====
    {
        SelSmem& S = *reinterpret_cast<SelSmem*>(sm);
        int warp = tid >> 5, lane = tid & 31;
        int nwork = g_nwork;

        for (int w = bid; w < nwork; w += NBLK3) {
            int ht = g_work[w];
            int h = ht >> 6, tile = ht & 63;
            int it0 = tile * TI;
            for (int b = 0; b < Bb; ++b) {
                int bh = b*Hh + h;
                for (int t = tid; t < TI*(Ss/32); t += 256) ((unsigned*)S.uni)[t] = 0u;

                for (int g = 0; g < Gg; ++g) {
                    for (int t = tid; t < Ss; t += 256) {
                        S.hks[t] = g_hk[(bh*Gg + g)*Ss + t];
                        S.sks[t] = g_sk[(h*Gg + g)*Ss + t];
                    }
                    if (tid < TI) {
                        S.myh[tid] = g_hq[(bh*Gg + g)*Ss + it0 + tid];
                        S.mys[tid] = g_sq[(h*Gg + g)*Ss + it0 + tid];
                    }
                    __syncthreads();

                    #pragma unroll
                    for (int iw = 0; iw < 2; ++iw) {
                        int ii = warp*2 + iw;
                        unsigned mh = S.myh[ii], ms = S.mys[ii];
                        int cnt = 0;
                        for (int c = 0; c < Ss/32; ++c) {
                            int j = c*32 + lane;
                            unsigned x = mh ^ S.hks[j];
                            bool m = (((x - 0x01010101u) & ~x & 0x80808080u) != 0u) && (S.sks[j] == ms);
                            unsigned bal = __ballot_sync(0xffffffffu, m);
                            if (lane == 0) S.comb[ii][c] = bal;
                            cnt += __popc(bal);
                        }
                        if (lane == 0) S.cnts[ii] = cnt;
                    }
                    __syncthreads();

                    for (int ii = 0; ii < TI; ++ii) {
                        if (S.cnts[ii] > KMAX) {
                            if (tid < GDd) S.qrow[tid] = g_qup[(bh*Ss + it0 + ii)*DKk + g*GDd + tid];
                            __syncthreads();
                            for (int j = tid; j < Ss; j += 256) {
                                unsigned key = 0u;
                                if ((S.comb[ii][j >> 5] >> (j & 31)) & 1u) {
                                    const float* kr = g_kup + (bh*Ss + j)*DKk + g*GDd;
                                    float sd = 0.f;
                                    #pragma unroll
                                    for (int d = 0; d < GDd; ++d) sd += S.qrow[d]*kr[d];
                                    unsigned u = __float_as_uint(sd);
                                    key = (u & 0x80000000u) ? ~u : (u | 0x80000000u);
                                }
                                S.keys[j] = key;
                            }
                            __syncthreads();
                            unsigned prefix = 0u, himask = 0u;
                            int want = KMAX;
                            for (int pass = 0; pass < 4; ++pass) {
                                int shift = 24 - 8*pass;
                                S.hist[tid] = 0u;
                                __syncthreads();
                                for (int j = tid; j < Ss; j += 256) {
                                    unsigned k2 = S.keys[j];
                                    if ((k2 & himask) == prefix) atomicAdd(&S.hist[(k2 >> shift) & 255], 1u);
                                }
                                __syncthreads();
                                for (int off = 1; off < 256; off <<= 1) {
                                    unsigned add = (tid + off < 256) ? S.hist[tid + off] : 0u;
                                    __syncthreads();
                                    S.hist[tid] += add;
                                    __syncthreads();
                                }
                                unsigned sfx = S.hist[tid];
                                unsigned nxt = (tid < 255) ? S.hist[tid + 1] : 0u;
                                if (sfx >= (unsigned)want && nxt < (unsigned)want) {
                                    S.sDigit = (unsigned)tid;
                                    S.sWant = want - (int)nxt;
                                }
                                __syncthreads();
                                prefix |= S.sDigit << shift;
                                himask |= 0xFFu << shift;
                                want = S.sWant;
                                __syncthreads();
                            }
                            unsigned thresh = prefix;
                            for (int j = tid; j < Ss; j += 256)
                                if (((S.comb[ii][j >> 5] >> (j & 31)) & 1u) && S.keys[j] >= thresh)
                                    atomicOr(&S.uni[ii][j >> 5], 1u << (j & 31));
                            __syncthreads();
                        }
                    }

                    for (int t = tid; t < TI*(Ss/32); t += 256) {
                        int ii = t >> 5, w2 = t & 31;
                        if (S.cnts[ii] <= KMAX) S.uni[ii][w2] |= S.comb[ii][w2];
                    }
                    __syncthreads();
                }

                #pragma unroll
                for (int iw = 0; iw < 2; ++iw) {
                    int ii = warp*2 + iw;
                    unsigned w32 = S.uni[ii][lane];
                    int pc = __popc(w32);
                    int inc = pc;
                    #pragma unroll
                    for (int off = 1; off < 32; off <<= 1) {
                        int v = __shfl_up_sync(0xffffffffu, inc, off);
                        if (lane >= off) inc += v;
                    }
                    int pos = inc - pc;
                    int outBase = (bh*Ss + it0 + ii)*KMAX;
                    unsigned w2 = w32;
                    while (w2 && pos < KMAX) {
                        int bit = __ffs(w2) - 1;
                        w2 &= w2 - 1u;
                        g_cand[outBase + pos] = lane*32 + bit;
                        ++pos;
                    }
                    int tot = __shfl_sync(0xffffffffu, inc, 31);
                    if (lane == 0) g_cnt[bh*Ss + it0 + ii] = min(tot, KMAX);
                }
                __syncthreads();
            }
        }
    }
    grid_barrier3();

    // ===== Phase C: sparse attention + on-demand vproj + output GEMM =====
    {
        AttnSmem& S = *reinterpret_cast<AttnSmem*>(sm);
        for (int rr = 0; rr < 16; ++rr) {
            int row = bid*16 + rr;
            int b = row >> 10, i = row & 1023;
            if (tid < Hh) S.cnt8[tid] = g_cnt[(b*Hh + tid)*Ss + i];
            __syncthreads();
            int any = 0;
            #pragma unroll
            for (int h2 = 0; h2 < Hh; ++h2) any |= S.cnt8[h2];
            float* orow = out + row*Dd;
            if (!any) {
                if (tid < 128) ((float4*)orow)[tid] = make_float4(0.f, 0.f, 0.f, 0.f);
                __syncthreads();
                continue;
            }
            for (int h2 = 0; h2 < Hh; ++h2) {
                int cn = S.cnt8[h2];
                if (cn == 0) {
                    if (tid < DKk) S.rowv[h2*DKk + tid] = 0.f;
                    __syncthreads();
                    continue;
                }
                int bh = b*Hh + h2;
                if (tid < DKk) S.q64[tid] = g_qup[(bh*Ss + i)*DKk + tid];
                if (tid < cn) S.cj[tid] = g_cand[(bh*Ss + i)*KMAX + tid];
                __syncthreads();
                float s = -3.4e38f;
                if (tid < cn) {
                    const float* kr = g_kup + (bh*Ss + S.cj[tid])*DKk;
                    float acc = 0.f;
                    #pragma unroll
                    for (int d = 0; d < DKk; ++d) acc += S.q64[d]*kr[d];
                    s = acc * 0.125f;
                }
                if (tid < DKk) S.red[tid] = s;
                __syncthreads();
                for (int off = 32; off >= 1; off >>= 1) {
                    if (tid < off) S.red[tid] = fmaxf(S.red[tid], S.red[tid + off]);
                    __syncthreads();
                }
                float mx = S.red[0];
                __syncthreads();
                float e = (tid < cn) ? expf(s - mx) : 0.f;
                if (tid < DKk) S.red[tid] = e;
                __syncthreads();
                for (int off = 32; off >= 1; off >>= 1) {
                    if (tid < off) S.red[tid] += S.red[tid + off];
                    __syncthreads();
                }
                float denom = S.red[0];
                if (tid < DKk) S.pp[tid] = e / denom;
                __syncthreads();
                for (int d = tid; d < Dd; d += 256) {
                    float a = 0.f;
                    for (int c = 0; c < cn; ++c) a += S.pp[c]*value[(b*Ss + S.cj[c])*Dd + d];
                    S.pv[d] = a;
                }
                __syncthreads();
                if (tid < DKk) {
                    float a = 0.f;
                    for (int d = 0; d < Dd; ++d) a += S.pv[d]*Wv[(h2*Dd + d)*DKk + tid];
                    S.rowv[h2*DKk + tid] = a;
                }
                __syncthreads();
            }
            float a0 = 0.f, a1 = 0.f;
            for (int k2 = 0; k2 < Hh*DKk; ++k2) {
                float rv = S.rowv[k2];
                if (rv == 0.f) continue;
                a0 += rv * Wo[k2*Dd + tid];
                a1 += rv * Wo[k2*Dd + tid + 256];
            }
            orow[tid] = a0;
            orow[tid + 256] = a1;
            __syncthreads();
        }
    }
}

// ---------------- launch -----------------------------------------------------------
extern "C" void kernel_launch(void* const* d_in, const int* in_sizes, int n_in,
                              void* d_out, int out_size) {
    const float* query = (const float*)d_in[0];
    const float* key   = (const float*)d_in[1];
    const float* value = (const float*)d_in[2];
    const float* Aq    = (const float*)d_in[3];
    const float* Bq    = (const float*)d_in[4];
    const float* Ak    = (const float*)d_in[5];
    const float* Bk    = (const float*)d_in[6];
    const float* Wv    = (const float*)d_in[7];
    const float* Wo    = (const float*)d_in[8];
    const float* lsh   = (const float*)d_in[9];
    float* out = (float*)d_out;

    k_lowrank_tc<<<dim3(32, KSPLIT, 2), 256>>>(query, key, Aq, Ak);
    k_upproj_hash<<<Bb*Hh*(Ss/16), 256>>>(Bq, Bk, lsh);
    k_tail<<<NBLK3, 256>>>(value, Wv, Wo, out);
}

// round 13
// speedup vs baseline: 1.4018x; 1.0698x over previous
// R13: identical to R12 source (infra-failure retry; comment-only delta).
#include <cuda_runtime.h>
#include <math.h>

#define Bb 2
#define Ss 1024
#define Dd 512
#define Hh 8
#define DKk 64
#define Rr 16
#define Gg 2
#define GDd 32
#define NHh 4
#define KMAX 64
#define KSPLIT 4
#define TI 16
#define NBLK3 128

// ---------------- scratch (device globals; no allocation allowed) ----------------
__device__ float g_qtmp[KSPLIT*Bb*Ss*Hh*Rr];   // [ks][b*S+s][h*16+r]
__device__ float g_ktmp[KSPLIT*Bb*Ss*Hh*Rr];
__device__ float g_qt16[Bb*Hh*Ss*Rr];          // summed low-rank coeffs
__device__ float g_kt16[Bb*Hh*Ss*Rr];
__device__ unsigned g_hq[Bb*Hh*Gg*Ss];
__device__ unsigned g_hk[Bb*Hh*Gg*Ss];
__device__ unsigned g_sq[Hh*Gg*Ss];
__device__ unsigned g_sk[Hh*Gg*Ss];
__device__ int g_cand[Bb*Hh*Ss*KMAX];
__device__ int g_cnt[Bb*Hh*Ss];
__device__ int g_work[Hh*(Ss/TI)];
__device__ int g_nwork;
__device__ int g_bar_count;
__device__ int g_bar_gen;

__device__ __forceinline__ unsigned f2tf32(float f) {
    unsigned u;
    asm("cvt.rna.tf32.f32 %0, %1;" : "=r"(u) : "f"(f));
    return u;
}

// ---------------- K1: dual low-rank GEMM, tf32 mma.sync, K-split, double-buffered --
// K-tile depth 16 per buffer -> 25.6KB static SMEM (under 48KB static limit).
__global__ __launch_bounds__(256)
void k_lowrank_tc(const float* __restrict__ q, const float* __restrict__ k,
                  const float* __restrict__ Aq, const float* __restrict__ Ak) {
    __shared__ unsigned As[2][16][68];    // [buf][k][m] tf32 bits
    __shared__ unsigned Bs[2][16][132];   // [buf][k][n]
    int rowt = blockIdx.x, ks = blockIdx.y, qk = blockIdx.z;
    const float* X = qk ? k : q;
    const float* W = qk ? Ak : Aq;
    float* O = (qk ? g_ktmp : g_qtmp) + ks * (Bb*Ss) * (Hh*Rr);
    int row0 = rowt * 64;
    int d_base = ks * (Dd / KSPLIT);
    int tid = threadIdx.x;
    int warp = tid >> 5, lane = tid & 31;
    int gid = lane >> 2, tig = lane & 3;
    int wr = warp >> 2, wc = warp & 3;
    float acc[2][4][4] = {};

    // per-thread load coordinates (64 rows x 16 k for A, 16 k x 128 n for B)
    int amA = tid >> 2, akA = (tid & 3) * 4;           // 256 thr * 1 float4 = 64*16 A
    int kB[2], nB[2];
    #pragma unroll
    for (int i = 0; i < 2; ++i) {
        int idx = tid*2 + i;
        kB[i] = idx >> 5; nB[i] = (idx & 31) * 4;      // 512 float4 = 16*128 B
    }

    float4 ra, rb[2];
    auto ldg_tile = [&](int kb) {
        ra = *(const float4*)&X[(row0 + amA)*Dd + d_base + kb + akA];
        #pragma unroll
        for (int i = 0; i < 2; ++i)
            rb[i] = *(const float4*)&W[(nB[i] >> 4)*(Dd*Rr) + (d_base + kb + kB[i])*Rr + (nB[i] & 15)];
    };
    auto stg_tile = [&](int buf) {
        As[buf][akA+0][amA] = f2tf32(ra.x);
        As[buf][akA+1][amA] = f2tf32(ra.y);
        As[buf][akA+2][amA] = f2tf32(ra.z);
        As[buf][akA+3][amA] = f2tf32(ra.w);
        #pragma unroll
        for (int i = 0; i < 2; ++i) {
            Bs[buf][kB[i]][nB[i]+0] = f2tf32(rb[i].x);
            Bs[buf][kB[i]][nB[i]+1] = f2tf32(rb[i].y);
            Bs[buf][kB[i]][nB[i]+2] = f2tf32(rb[i].z);
            Bs[buf][kB[i]][nB[i]+3] = f2tf32(rb[i].w);
        }
    };

    ldg_tile(0);
    stg_tile(0);
    __syncthreads();

    #pragma unroll
    for (int it = 0; it < 8; ++it) {
        int cur = it & 1;
        if (it < 7) ldg_tile((it + 1) * 16);     // overlap next-tile loads with mma
        #pragma unroll
        for (int kks = 0; kks < 2; ++kks) {
            int k0 = kks * 8;
            unsigned a[2][4], b[4][2];
            #pragma unroll
            for (int mt = 0; mt < 2; ++mt) {
                int m0 = wr*32 + mt*16;
                a[mt][0] = As[cur][k0+tig  ][m0+gid  ];
                a[mt][1] = As[cur][k0+tig  ][m0+gid+8];
                a[mt][2] = As[cur][k0+tig+4][m0+gid  ];
                a[mt][3] = As[cur][k0+tig+4][m0+gid+8];
            }
            #pragma unroll
            for (int nt = 0; nt < 4; ++nt) {
                int n0 = wc*32 + nt*8;
                b[nt][0] = Bs[cur][k0+tig  ][n0+gid];
                b[nt][1] = Bs[cur][k0+tig+4][n0+gid];
            }
            #pragma unroll
            for (int mt = 0; mt < 2; ++mt)
                #pragma unroll
                for (int nt = 0; nt < 4; ++nt) {
                    float* c = acc[mt][nt];
                    asm volatile(
                        "mma.sync.aligned.m16n8k8.row.col.f32.tf32.tf32.f32 "
                        "{%0,%1,%2,%3}, {%4,%5,%6,%7}, {%8,%9}, {%0,%1,%2,%3};"
                        : "+f"(c[0]), "+f"(c[1]), "+f"(c[2]), "+f"(c[3])
                        : "r"(a[mt][0]), "r"(a[mt][1]), "r"(a[mt][2]), "r"(a[mt][3]),
                          "r"(b[nt][0]), "r"(b[nt][1]));
                }
        }
        __syncthreads();
        if (it < 7) {
            stg_tile(cur ^ 1);
            __syncthreads();
        }
    }

    #pragma unroll
    for (int mt = 0; mt < 2; ++mt)
        #pragma unroll
        for (int nt = 0; nt < 4; ++nt) {
            int m0 = row0 + wr*32 + mt*16, n0 = wc*32 + nt*8;
            O[(m0+gid  )*(Hh*Rr) + n0 + 2*tig  ] = acc[mt][nt][0];
            O[(m0+gid  )*(Hh*Rr) + n0 + 2*tig+1] = acc[mt][nt][1];
            O[(m0+gid+8)*(Hh*Rr) + n0 + 2*tig  ] = acc[mt][nt][2];
            O[(m0+gid+8)*(Hh*Rr) + n0 + 2*tig+1] = acc[mt][nt][3];
        }
}

// ---------------- K2: coeff sum + LSH hash + sign pack (16 s/block) ----------------
__global__ void k_upproj_hash(const float* __restrict__ Bq, const float* __restrict__ Bk,
                              const float* __restrict__ lsh) {
    __shared__ float Bqs[Rr][DKk];
    __shared__ float Bks[Rr][DKk];
    __shared__ float qts[4][Rr];
    __shared__ float kts[4][Rr];
    __shared__ float Ps[Gg*GDd*NHh];

    int blk = blockIdx.x;
    int s0 = (blk % (Ss/16)) * 16;
    int h = (blk / (Ss/16)) % Hh;
    int b = blk / ((Ss/16) * Hh);
    int tid = threadIdx.x;

    if (blk == 0 && tid == 0) g_nwork = 0;     // reset worklist for K3
    for (int t = tid; t < Rr*DKk; t += 256) {
        Bqs[t >> 6][t & 63] = Bq[h*Rr*DKk + t];
        Bks[t >> 6][t & 63] = Bk[h*Rr*DKk + t];
    }
    if (tid < Gg*GDd*NHh) Ps[tid] = lsh[h*(Gg*GDd*NHh) + tid];

    int kk = tid & 63;
    int sl2 = tid >> 6;
    int g = kk >> 5;
    int d = kk & 31;
    int bh = b*Hh + h;

    for (int ss = 0; ss < 16; ss += 4) {
        if (tid < 128) {
            int sl = tid >> 5, r = (tid >> 1) & 15, qk = tid & 1;
            int row = b*Ss + s0 + ss + sl;
            const float* base = (qk ? g_ktmp : g_qtmp) + row*(Hh*Rr) + h*Rr + r;
            const int st = (Bb*Ss)*(Hh*Rr);
            float v = base[0] + base[st] + base[2*st] + base[3*st];
            int gi = (bh*Ss + s0 + ss + sl)*Rr + r;
            if (qk) { kts[sl][r] = v; g_kt16[gi] = v; }
            else    { qts[sl][r] = v; g_qt16[gi] = v; }
        }
        __syncthreads();

        int s = s0 + ss + sl2;
        float qv = 0.f, kv = 0.f;
        #pragma unroll
        for (int r = 0; r < Rr; ++r) {
            qv += qts[sl2][r] * Bqs[r][kk];
            kv += kts[sl2][r] * Bks[r][kk];
        }

        unsigned bq = __ballot_sync(0xffffffffu, qv > 0.f);
        unsigned bk2 = __ballot_sync(0xffffffffu, kv > 0.f);

        float hq[NHh], hk[NHh];
        #pragma unroll
        for (int n = 0; n < NHh; ++n) {
            float p = Ps[(g*GDd + d)*NHh + n];
            hq[n] = qv * p;
            hk[n] = kv * p;
        }
        #pragma unroll
        for (int off = 16; off >= 1; off >>= 1) {
            #pragma unroll
            for (int n = 0; n < NHh; ++n) {
                hq[n] += __shfl_xor_sync(0xffffffffu, hq[n], off);
                hk[n] += __shfl_xor_sync(0xffffffffu, hk[n], off);
            }
        }
        if (d == 0) {
            unsigned pq = 0u, pk = 0u;
            #pragma unroll
            for (int n = 0; n < NHh; ++n) {
                pq |= ((unsigned)(((int)floorf(hq[n]*0.25f)) & 63)) << (8*n);
                pk |= ((unsigned)(((int)floorf(hk[n]*0.25f)) & 63)) << (8*n);
            }
            g_hq[(bh*Gg + g)*Ss + s] = pq;
            g_hk[(bh*Gg + g)*Ss + s] = pk;
            if (b == Bb - 1) {
                g_sq[(h*Gg + g)*Ss + s] = bq;
                g_sk[(h*Gg + g)*Ss + s] = bk2;
            }
        }
        __syncthreads();
    }
}

// ---------------- K3: persistent trie + select + attn_out (128 blocks) -------------
__device__ __forceinline__ void grid_barrier3() {
    __syncthreads();
    __threadfence();
    __syncthreads();
    if (threadIdx.x == 0) {
        int gen = *(volatile int*)&g_bar_gen;
        if (atomicAdd(&g_bar_count, 1) == NBLK3 - 1) {
            g_bar_count = 0;
            __threadfence();
            atomicExch(&g_bar_gen, gen + 1);
        } else {
            long long spin = 0;
            while (*(volatile int*)&g_bar_gen == gen) {
                if (((++spin) & 255) == 0) __nanosleep(64);
                if (spin > (1LL << 31)) break;   // safety valve: never hang the box
            }
        }
        __threadfence();
    }
    __syncthreads();
}

struct TrieSmem { unsigned tsign[2048]; int tj[2048];
                  unsigned rowflag[Ss/32]; unsigned flags[Ss/TI]; int fallback; };
struct SelSmem  { unsigned hks[Ss]; unsigned sks[Ss];
                  unsigned comb[TI][Ss/32]; unsigned uni[TI][Ss/32];
                  unsigned keys[Ss]; unsigned hist[256];
                  unsigned myh[TI], mys[TI]; int cnts[TI];
                  float qrow[GDd]; float qBk[Rr]; unsigned sDigit; int sWant; };
struct AttnSmem { float pv[Dd]; float rowv[Hh*DKk]; float q64[DKk]; float qB[Rr];
                  float red[DKk]; float pp[KMAX]; int cj[KMAX]; int cnt8[Hh]; };

__global__ __launch_bounds__(256, 1)
void k_tail(const float* __restrict__ value, const float* __restrict__ Wv,
            const float* __restrict__ Wo, const float* __restrict__ Bq,
            const float* __restrict__ Bk, float* __restrict__ out) {
    __shared__ __align__(16) unsigned char sm[18816];
    int bid = blockIdx.x;
    int tid = threadIdx.x;

    // ===== Phase A: trie prefilter + worklist (blocks 0..7) =====
    if (bid < Hh) {
        TrieSmem& S = *reinterpret_cast<TrieSmem*>(sm);
        int h = bid;
        if (tid == 0) S.fallback = 0;
        for (int t = tid; t < Ss/32; t += 256) S.rowflag[t] = 0u;
        for (int g = 0; g < Gg; ++g) {
            for (int t = tid; t < 2048; t += 256) S.tj[t] = 0;
            __syncthreads();
            for (int j = tid; j < Ss; j += 256) {
                unsigned s = g_sk[(h*Gg + g)*Ss + j];
                unsigned slot = (s * 2654435761u >> 16) & 2047u;
                bool ok = false;
                for (int p = 0; p < 4096; ++p) {
                    if (atomicCAS(&S.tj[slot], 0, (int)j + 1) == 0) { S.tsign[slot] = s; ok = true; break; }
                    slot = (slot + 1) & 2047u;
                }
                if (!ok) atomicExch(&S.fallback, 1);
            }
            __syncthreads();
            for (int i = tid; i < Ss; i += 256) {
                unsigned s = g_sq[(h*Gg + g)*Ss + i];
                unsigned slot = (s * 2654435761u >> 16) & 2047u;
                bool m = true;
                for (int p = 0; p < 2048; ++p) {
                    int occ = S.tj[slot];
                    if (occ == 0) { m = false; break; }
                    if (S.tsign[slot] == s) { m = true; break; }
                    slot = (slot + 1) & 2047u;
                }
                if (m) atomicOr(&S.rowflag[i >> 5], 1u << (i & 31));
            }
            __syncthreads();
        }
        if (tid < Ss/TI) {
            unsigned w = S.rowflag[tid >> 1];
            unsigned bits = (w >> ((tid & 1) * 16)) & 0xFFFFu;
            unsigned f = (bits || S.fallback) ? 1u : 0u;
            S.flags[tid] = f;
            if (f) {
                int p = atomicAdd(&g_nwork, 1);
                g_work[p] = (h << 6) | tid;
            }
        }
        __syncthreads();
        for (int t = tid; t < Bb*Ss; t += 256) {
            int b2 = t >> 10, s = t & 1023;
            if (!S.flags[s >> 4]) g_cnt[(b2*Hh + h)*Ss + s] = 0;
        }
    }
    grid_barrier3();

    // ===== Phase B: candidate selection (worklist drain) =====
    {
        SelSmem& S = *reinterpret_cast<SelSmem*>(sm);
        int warp = tid >> 5, lane = tid & 31;
        int nwork = g_nwork;

        for (int w = bid; w < nwork; w += NBLK3) {
            int ht = g_work[w];
            int h = ht >> 6, tile = ht & 63;
            int it0 = tile * TI;
            for (int b = 0; b < Bb; ++b) {
                int bh = b*Hh + h;
                for (int t = tid; t < TI*(Ss/32); t += 256) ((unsigned*)S.uni)[t] = 0u;

                for (int g = 0; g < Gg; ++g) {
                    for (int t = tid; t < Ss; t += 256) {
                        S.hks[t] = g_hk[(bh*Gg + g)*Ss + t];
                        S.sks[t] = g_sk[(h*Gg + g)*Ss + t];
                    }
                    if (tid < TI) {
                        S.myh[tid] = g_hq[(bh*Gg + g)*Ss + it0 + tid];
                        S.mys[tid] = g_sq[(h*Gg + g)*Ss + it0 + tid];
                    }
                    __syncthreads();

                    #pragma unroll
                    for (int iw = 0; iw < 2; ++iw) {
                        int ii = warp*2 + iw;
                        unsigned mh = S.myh[ii], ms = S.mys[ii];
                        int cnt = 0;
                        for (int c = 0; c < Ss/32; ++c) {
                            int j = c*32 + lane;
                            unsigned x = mh ^ S.hks[j];
                            bool m = (((x - 0x01010101u) & ~x & 0x80808080u) != 0u) && (S.sks[j] == ms);
                            unsigned bal = __ballot_sync(0xffffffffu, m);
                            if (lane == 0) S.comb[ii][c] = bal;
                            cnt += __popc(bal);
                        }
                        if (lane == 0) S.cnts[ii] = cnt;
                    }
                    __syncthreads();

                    // rare path: reconstruct group-sim scores from low-rank coeffs
                    for (int ii = 0; ii < TI; ++ii) {
                        if (S.cnts[ii] > KMAX) {
                            if (tid < GDd) {
                                const float* qt = g_qt16 + (bh*Ss + it0 + ii)*Rr;
                                float a = 0.f;
                                #pragma unroll
                                for (int r = 0; r < Rr; ++r)
                                    a += qt[r] * Bq[(h*Rr + r)*DKk + g*GDd + tid];
                                S.qrow[tid] = a;
                            }
                            __syncthreads();
                            if (tid < Rr) {
                                float a = 0.f;
                                #pragma unroll
                                for (int d = 0; d < GDd; ++d)
                                    a += S.qrow[d] * Bk[(h*Rr + tid)*DKk + g*GDd + d];
                                S.qBk[tid] = a;
                            }
                            __syncthreads();
                            for (int j = tid; j < Ss; j += 256) {
                                unsigned key = 0u;
                                if ((S.comb[ii][j >> 5] >> (j & 31)) & 1u) {
                                    const float* kt = g_kt16 + (bh*Ss + j)*Rr;
                                    float sd = 0.f;
                                    #pragma unroll
                                    for (int r = 0; r < Rr; ++r) sd += kt[r]*S.qBk[r];
                                    unsigned u = __float_as_uint(sd);
                                    key = (u & 0x80000000u) ? ~u : (u | 0x80000000u);
                                }
                                S.keys[j] = key;
                            }
                            __syncthreads();
                            unsigned prefix = 0u, himask = 0u;
                            int want = KMAX;
                            for (int pass = 0; pass < 4; ++pass) {
                                int shift = 24 - 8*pass;
                                S.hist[tid] = 0u;
                                __syncthreads();
                                for (int j = tid; j < Ss; j += 256) {
                                    unsigned k2 = S.keys[j];
                                    if ((k2 & himask) == prefix) atomicAdd(&S.hist[(k2 >> shift) & 255], 1u);
                                }
                                __syncthreads();
                                for (int off = 1; off < 256; off <<= 1) {
                                    unsigned add = (tid + off < 256) ? S.hist[tid + off] : 0u;
                                    __syncthreads();
                                    S.hist[tid] += add;
                                    __syncthreads();
                                }
                                unsigned sfx = S.hist[tid];
                                unsigned nxt = (tid < 255) ? S.hist[tid + 1] : 0u;
                                if (sfx >= (unsigned)want && nxt < (unsigned)want) {
                                    S.sDigit = (unsigned)tid;
                                    S.sWant = want - (int)nxt;
                                }
                                __syncthreads();
                                prefix |= S.sDigit << shift;
                                himask |= 0xFFu << shift;
                                want = S.sWant;
                                __syncthreads();
                            }
                            unsigned thresh = prefix;
                            for (int j = tid; j < Ss; j += 256)
                                if (((S.comb[ii][j >> 5] >> (j & 31)) & 1u) && S.keys[j] >= thresh)
                                    atomicOr(&S.uni[ii][j >> 5], 1u << (j & 31));
                            __syncthreads();
                        }
                    }

                    for (int t = tid; t < TI*(Ss/32); t += 256) {
                        int ii = t >> 5, w2 = t & 31;
                        if (S.cnts[ii] <= KMAX) S.uni[ii][w2] |= S.comb[ii][w2];
                    }
                    __syncthreads();
                }

                #pragma unroll
                for (int iw = 0; iw < 2; ++iw) {
                    int ii = warp*2 + iw;
                    unsigned w32 = S.uni[ii][lane];
                    int pc = __popc(w32);
                    int inc = pc;
                    #pragma unroll
                    for (int off = 1; off < 32; off <<= 1) {
                        int v = __shfl_up_sync(0xffffffffu, inc, off);
                        if (lane >= off) inc += v;
                    }
                    int pos = inc - pc;
                    int outBase = (bh*Ss + it0 + ii)*KMAX;
                    unsigned w2 = w32;
                    while (w2 && pos < KMAX) {
                        int bit = __ffs(w2) - 1;
                        w2 &= w2 - 1u;
                        g_cand[outBase + pos] = lane*32 + bit;
                        ++pos;
                    }
                    int tot = __shfl_sync(0xffffffffu, inc, 31);
                    if (lane == 0) g_cnt[bh*Ss + it0 + ii] = min(tot, KMAX);
                }
                __syncthreads();
            }
        }
    }
    grid_barrier3();

    // ===== Phase C: sparse attention + on-demand projections + output GEMM =====
    {
        AttnSmem& S = *reinterpret_cast<AttnSmem*>(sm);
        for (int rr = 0; rr < 16; ++rr) {
            int row = bid*16 + rr;
            int b = row >> 10, i = row & 1023;
            if (tid < Hh) S.cnt8[tid] = g_cnt[(b*Hh + tid)*Ss + i];
            __syncthreads();
            int any = 0;
            #pragma unroll
            for (int h2 = 0; h2 < Hh; ++h2) any |= S.cnt8[h2];
            float* orow = out + row*Dd;
            if (!any) {
                if (tid < 128) ((float4*)orow)[tid] = make_float4(0.f, 0.f, 0.f, 0.f);
                __syncthreads();
                continue;
            }
            for (int h2 = 0; h2 < Hh; ++h2) {
                int cn = S.cnt8[h2];
                if (cn == 0) {
                    if (tid < DKk) S.rowv[h2*DKk + tid] = 0.f;
                    __syncthreads();
                    continue;
                }
                int bh = b*Hh + h2;
                // reconstruct q_up row from low-rank coeffs
                if (tid < DKk) {
                    const float* qt = g_qt16 + (bh*Ss + i)*Rr;
                    float a = 0.f;
                    #pragma unroll
                    for (int r = 0; r < Rr; ++r) a += qt[r]*Bq[(h2*Rr + r)*DKk + tid];
                    S.q64[tid] = a;
                }
                if (tid < cn) S.cj[tid] = g_cand[(bh*Ss + i)*KMAX + tid];
                __syncthreads();
                if (tid < Rr) {
                    float a = 0.f;
                    #pragma unroll
                    for (int d = 0; d < DKk; ++d) a += S.q64[d]*Bk[(h2*Rr + tid)*DKk + d];
                    S.qB[tid] = a;
                }
                __syncthreads();
                float s = -3.4e38f;
                if (tid < cn) {
                    const float* kt = g_kt16 + (bh*Ss + S.cj[tid])*Rr;
                    float acc = 0.f;
                    #pragma unroll
                    for (int r = 0; r < Rr; ++r) acc += kt[r]*S.qB[r];
                    s = acc * 0.125f;
                }
                if (tid < DKk) S.red[tid] = s;
                __syncthreads();
                for (int off = 32; off >= 1; off >>= 1) {
                    if (tid < off) S.red[tid] = fmaxf(S.red[tid], S.red[tid + off]);
                    __syncthreads();
                }
                float mx = S.red[0];
                __syncthreads();
                float e = (tid < cn) ? expf(s - mx) : 0.f;
                if (tid < DKk) S.red[tid] = e;
                __syncthreads();
                for (int off = 32; off >= 1; off >>= 1) {
                    if (tid < off) S.red[tid] += S.red[tid + off];
                    __syncthreads();
                }
                float denom = S.red[0];
                if (tid < DKk) S.pp[tid] = e / denom;
                __syncthreads();
                for (int d = tid; d < Dd; d += 256) {
                    float a = 0.f;
                    for (int c = 0; c < cn; ++c) a += S.pp[c]*value[(b*Ss + S.cj[c])*Dd + d];
                    S.pv[d] = a;
                }
                __syncthreads();
                if (tid < DKk) {
                    float a = 0.f;
                    for (int d = 0; d < Dd; ++d) a += S.pv[d]*Wv[(h2*Dd + d)*DKk + tid];
                    S.rowv[h2*DKk + tid] = a;
                }
                __syncthreads();
            }
            float a0 = 0.f, a1 = 0.f;
            for (int k2 = 0; k2 < Hh*DKk; ++k2) {
                float rv = S.rowv[k2];
                if (rv == 0.f) continue;
                a0 += rv * Wo[k2*Dd + tid];
                a1 += rv * Wo[k2*Dd + tid + 256];
            }
            orow[tid] = a0;
            orow[tid + 256] = a1;
            __syncthreads();
        }
    }
}

// ---------------- launch -----------------------------------------------------------
extern "C" void kernel_launch(void* const* d_in, const int* in_sizes, int n_in,
                              void* d_out, int out_size) {
    const float* query = (const float*)d_in[0];
    const float* key   = (const float*)d_in[1];
    const float* value = (const float*)d_in[2];
    const float* Aq    = (const float*)d_in[3];
    const float* Bq    = (const float*)d_in[4];
    const float* Ak    = (const float*)d_in[5];
    const float* Bk    = (const float*)d_in[6];
    const float* Wv    = (const float*)d_in[7];
    const float* Wo    = (const float*)d_in[8];
    const float* lsh   = (const float*)d_in[9];
    float* out = (float*)d_out;

    k_lowrank_tc<<<dim3(32, KSPLIT, 2), 256>>>(query, key, Aq, Ak);
    k_upproj_hash<<<Bb*Hh*(Ss/16), 256>>>(Bq, Bk, lsh);
    k_tail<<<NBLK3, 256>>>(value, Wv, Wo, Bq, Bk, out);
}

// round 14
// speedup vs baseline: 1.4424x; 1.0290x over previous
#include <cuda_runtime.h>
#include <math.h>

#define Bb 2
#define Ss 1024
#define Dd 512
#define Hh 8
#define DKk 64
#define Rr 16
#define Gg 2
#define GDd 32
#define NHh 4
#define KMAX 64
#define KSPLIT 2
#define TI 16
#define NBLK3 128

// ---------------- scratch (device globals; no allocation allowed) ----------------
__device__ float g_qtmp[KSPLIT*Bb*Ss*Hh*Rr];   // [ks][b*S+s][h*16+r]
__device__ float g_ktmp[KSPLIT*Bb*Ss*Hh*Rr];
__device__ float g_qt16[Bb*Hh*Ss*Rr];          // summed low-rank coeffs
__device__ float g_kt16[Bb*Hh*Ss*Rr];
__device__ unsigned g_hq[Bb*Hh*Gg*Ss];
__device__ unsigned g_hk[Bb*Hh*Gg*Ss];
__device__ unsigned g_sq[Hh*Gg*Ss];
__device__ unsigned g_sk[Hh*Gg*Ss];
__device__ int g_cand[Bb*Hh*Ss*KMAX];
__device__ int g_cnt[Bb*Hh*Ss];
__device__ int g_work[Hh*(Ss/TI)];
__device__ int g_nwork;
__device__ int g_bar_count;
__device__ int g_bar_gen;

__device__ __forceinline__ void cp_async16(unsigned saddr, const void* gptr) {
    asm volatile("cp.async.ca.shared.global [%0], [%1], 16;" :: "r"(saddr), "l"(gptr));
}

// ---------------- K1: dual low-rank GEMM, tf32 mma.sync, cp.async 2-stage pipe -----
// A kept [m][k] row-major (pad 20 -> conflict-free fragment reads); raw fp32 bits
// fed to mma.tf32 (HW truncation; within tolerance). KSPLIT=2, 128 blocks.
__global__ __launch_bounds__(256)
void k_lowrank_tc(const float* __restrict__ q, const float* __restrict__ k,
                  const float* __restrict__ Aq, const float* __restrict__ Ak) {
    __shared__ float Af[2][64][20];     // [buf][m][k]
    __shared__ float Bf[2][16][132];    // [buf][k][n]
    int rowt = blockIdx.x, ks = blockIdx.y, qk = blockIdx.z;
    const float* X = qk ? k : q;
    const float* W = qk ? Ak : Aq;
    float* O = (qk ? g_ktmp : g_qtmp) + ks * (Bb*Ss) * (Hh*Rr);
    int row0 = rowt * 64;
    int d_base = ks * (Dd / KSPLIT);    // 256-deep chunk
    int tid = threadIdx.x;
    int warp = tid >> 5, lane = tid & 31;
    int gid = lane >> 2, tig = lane & 3;
    int wr = warp >> 2, wc = warp & 3;
    float acc[2][4][4] = {};

    // per-thread async-copy coordinates
    int amA = tid >> 2, akA = (tid & 3) * 4;           // A: 256 float4 = 64m x 16k
    int kB[2], nB[2];
    #pragma unroll
    for (int i = 0; i < 2; ++i) {
        int idx = tid*2 + i;
        kB[i] = idx >> 5; nB[i] = (idx & 31) * 4;      // B: 512 float4 = 16k x 128n
    }
    unsigned sA[2], sB[2][2];
    #pragma unroll
    for (int bf = 0; bf < 2; ++bf) {
        sA[bf] = (unsigned)__cvta_generic_to_shared(&Af[bf][amA][akA]);
        #pragma unroll
        for (int i = 0; i < 2; ++i)
            sB[bf][i] = (unsigned)__cvta_generic_to_shared(&Bf[bf][kB[i]][nB[i]]);
    }

    auto issue_tile = [&](int kb, int bf) {
        cp_async16(sA[bf], &X[(row0 + amA)*Dd + d_base + kb + akA]);
        #pragma unroll
        for (int i = 0; i < 2; ++i)
            cp_async16(sB[bf][i],
                       &W[(nB[i] >> 4)*(Dd*Rr) + (d_base + kb + kB[i])*Rr + (nB[i] & 15)]);
        asm volatile("cp.async.commit_group;");
    };

    issue_tile(0, 0);

    const int NT = (Dd / KSPLIT) / 16;   // 16 tiles
    for (int it = 0; it < NT; ++it) {
        int cur = it & 1;
        if (it < NT - 1) {
            issue_tile((it + 1) * 16, cur ^ 1);
            asm volatile("cp.async.wait_group 1;");
        } else {
            asm volatile("cp.async.wait_group 0;");
        }
        __syncthreads();
        #pragma unroll
        for (int kks = 0; kks < 2; ++kks) {
            int k0 = kks * 8;
            unsigned a[2][4], b[4][2];
            #pragma unroll
            for (int mt = 0; mt < 2; ++mt) {
                int m0 = wr*32 + mt*16;
                a[mt][0] = __float_as_uint(Af[cur][m0+gid  ][k0+tig  ]);
                a[mt][1] = __float_as_uint(Af[cur][m0+gid+8][k0+tig  ]);
                a[mt][2] = __float_as_uint(Af[cur][m0+gid  ][k0+tig+4]);
                a[mt][3] = __float_as_uint(Af[cur][m0+gid+8][k0+tig+4]);
            }
            #pragma unroll
            for (int nt = 0; nt < 4; ++nt) {
                int n0 = wc*32 + nt*8;
                b[nt][0] = __float_as_uint(Bf[cur][k0+tig  ][n0+gid]);
                b[nt][1] = __float_as_uint(Bf[cur][k0+tig+4][n0+gid]);
            }
            #pragma unroll
            for (int mt = 0; mt < 2; ++mt)
                #pragma unroll
                for (int nt = 0; nt < 4; ++nt) {
                    float* c = acc[mt][nt];
                    asm volatile(
                        "mma.sync.aligned.m16n8k8.row.col.f32.tf32.tf32.f32 "
                        "{%0,%1,%2,%3}, {%4,%5,%6,%7}, {%8,%9}, {%0,%1,%2,%3};"
                        : "+f"(c[0]), "+f"(c[1]), "+f"(c[2]), "+f"(c[3])
                        : "r"(a[mt][0]), "r"(a[mt][1]), "r"(a[mt][2]), "r"(a[mt][3]),
                          "r"(b[nt][0]), "r"(b[nt][1]));
                }
        }
        __syncthreads();
    }

    #pragma unroll
    for (int mt = 0; mt < 2; ++mt)
        #pragma unroll
        for (int nt = 0; nt < 4; ++nt) {
            int m0 = row0 + wr*32 + mt*16, n0 = wc*32 + nt*8;
            O[(m0+gid  )*(Hh*Rr) + n0 + 2*tig  ] = acc[mt][nt][0];
            O[(m0+gid  )*(Hh*Rr) + n0 + 2*tig+1] = acc[mt][nt][1];
            O[(m0+gid+8)*(Hh*Rr) + n0 + 2*tig  ] = acc[mt][nt][2];
            O[(m0+gid+8)*(Hh*Rr) + n0 + 2*tig+1] = acc[mt][nt][3];
        }
}

// ---------------- K2: coeff sum + LSH hash + sign pack (16 s/block) ----------------
__global__ void k_upproj_hash(const float* __restrict__ Bq, const float* __restrict__ Bk,
                              const float* __restrict__ lsh) {
    __shared__ float Bqs[Rr][DKk];
    __shared__ float Bks[Rr][DKk];
    __shared__ float qts[4][Rr];
    __shared__ float kts[4][Rr];
    __shared__ float Ps[Gg*GDd*NHh];

    int blk = blockIdx.x;
    int s0 = (blk % (Ss/16)) * 16;
    int h = (blk / (Ss/16)) % Hh;
    int b = blk / ((Ss/16) * Hh);
    int tid = threadIdx.x;

    if (blk == 0 && tid == 0) g_nwork = 0;     // reset worklist for K3
    for (int t = tid; t < Rr*DKk; t += 256) {
        Bqs[t >> 6][t & 63] = Bq[h*Rr*DKk + t];
        Bks[t >> 6][t & 63] = Bk[h*Rr*DKk + t];
    }
    if (tid < Gg*GDd*NHh) Ps[tid] = lsh[h*(Gg*GDd*NHh) + tid];

    int kk = tid & 63;
    int sl2 = tid >> 6;
    int g = kk >> 5;
    int d = kk & 31;
    int bh = b*Hh + h;

    for (int ss = 0; ss < 16; ss += 4) {
        if (tid < 128) {
            int sl = tid >> 5, r = (tid >> 1) & 15, qk = tid & 1;
            int row = b*Ss + s0 + ss + sl;
            const float* base = (qk ? g_ktmp : g_qtmp) + row*(Hh*Rr) + h*Rr + r;
            const int st = (Bb*Ss)*(Hh*Rr);
            float v = base[0] + base[st];           // KSPLIT=2 partial sum
            int gi = (bh*Ss + s0 + ss + sl)*Rr + r;
            if (qk) { kts[sl][r] = v; g_kt16[gi] = v; }
            else    { qts[sl][r] = v; g_qt16[gi] = v; }
        }
        __syncthreads();

        int s = s0 + ss + sl2;
        float qv = 0.f, kv = 0.f;
        #pragma unroll
        for (int r = 0; r < Rr; ++r) {
            qv += qts[sl2][r] * Bqs[r][kk];
            kv += kts[sl2][r] * Bks[r][kk];
        }

        unsigned bq = __ballot_sync(0xffffffffu, qv > 0.f);
        unsigned bk2 = __ballot_sync(0xffffffffu, kv > 0.f);

        float hq[NHh], hk[NHh];
        #pragma unroll
        for (int n = 0; n < NHh; ++n) {
            float p = Ps[(g*GDd + d)*NHh + n];
            hq[n] = qv * p;
            hk[n] = kv * p;
        }
        #pragma unroll
        for (int off = 16; off >= 1; off >>= 1) {
            #pragma unroll
            for (int n = 0; n < NHh; ++n) {
                hq[n] += __shfl_xor_sync(0xffffffffu, hq[n], off);
                hk[n] += __shfl_xor_sync(0xffffffffu, hk[n], off);
            }
        }
        if (d == 0) {
            unsigned pq = 0u, pk = 0u;
            #pragma unroll
            for (int n = 0; n < NHh; ++n) {
                pq |= ((unsigned)(((int)floorf(hq[n]*0.25f)) & 63)) << (8*n);
                pk |= ((unsigned)(((int)floorf(hk[n]*0.25f)) & 63)) << (8*n);
            }
            g_hq[(bh*Gg + g)*Ss + s] = pq;
            g_hk[(bh*Gg + g)*Ss + s] = pk;
            if (b == Bb - 1) {
                g_sq[(h*Gg + g)*Ss + s] = bq;
                g_sk[(h*Gg + g)*Ss + s] = bk2;
            }
        }
        __syncthreads();
    }
}

// ---------------- K3: persistent trie + select + attn_out (128 blocks) -------------
__device__ __forceinline__ void grid_barrier3() {
    __syncthreads();
    __threadfence();
    __syncthreads();
    if (threadIdx.x == 0) {
        int gen = *(volatile int*)&g_bar_gen;
        if (atomicAdd(&g_bar_count, 1) == NBLK3 - 1) {
            g_bar_count = 0;
            __threadfence();
            atomicExch(&g_bar_gen, gen + 1);
        } else {
            long long spin = 0;
            while (*(volatile int*)&g_bar_gen == gen) {
                if (((++spin) & 255) == 0) __nanosleep(64);
                if (spin > (1LL << 31)) break;   // safety valve: never hang the box
            }
        }
        __threadfence();
    }
    __syncthreads();
}

struct TrieSmem { unsigned tsign[2048]; int tj[2048];
                  unsigned rowflag[Ss/32]; unsigned flags[Ss/TI]; int fallback; };
struct SelSmem  { unsigned hks[Ss]; unsigned sks[Ss];
                  unsigned comb[TI][Ss/32]; unsigned uni[TI][Ss/32];
                  unsigned keys[Ss]; unsigned hist[256];
                  unsigned myh[TI], mys[TI]; int cnts[TI];
                  float qrow[GDd]; float qBk[Rr]; unsigned sDigit; int sWant; };
struct AttnSmem { float pv[Dd]; float rowv[Hh*DKk]; float q64[DKk]; float qB[Rr];
                  float red[DKk]; float pp[KMAX]; int cj[KMAX]; int cnt8[Hh]; };

__global__ __launch_bounds__(256, 1)
void k_tail(const float* __restrict__ value, const float* __restrict__ Wv,
            const float* __restrict__ Wo, const float* __restrict__ Bq,
            const float* __restrict__ Bk, float* __restrict__ out) {
    __shared__ __align__(16) unsigned char sm[18816];
    int bid = blockIdx.x;
    int tid = threadIdx.x;

    // ===== Phase A: trie prefilter + worklist (blocks 0..7) =====
    if (bid < Hh) {
        TrieSmem& S = *reinterpret_cast<TrieSmem*>(sm);
        int h = bid;
        if (tid == 0) S.fallback = 0;
        for (int t = tid; t < Ss/32; t += 256) S.rowflag[t] = 0u;
        for (int g = 0; g < Gg; ++g) {
            for (int t = tid; t < 2048; t += 256) S.tj[t] = 0;
            __syncthreads();
            for (int j = tid; j < Ss; j += 256) {
                unsigned s = g_sk[(h*Gg + g)*Ss + j];
                unsigned slot = (s * 2654435761u >> 16) & 2047u;
                bool ok = false;
                for (int p = 0; p < 4096; ++p) {
                    if (atomicCAS(&S.tj[slot], 0, (int)j + 1) == 0) { S.tsign[slot] = s; ok = true; break; }
                    slot = (slot + 1) & 2047u;
                }
                if (!ok) atomicExch(&S.fallback, 1);
            }
            __syncthreads();
            for (int i = tid; i < Ss; i += 256) {
                unsigned s = g_sq[(h*Gg + g)*Ss + i];
                unsigned slot = (s * 2654435761u >> 16) & 2047u;
                bool m = true;
                for (int p = 0; p < 2048; ++p) {
                    int occ = S.tj[slot];
                    if (occ == 0) { m = false; break; }
                    if (S.tsign[slot] == s) { m = true; break; }
                    slot = (slot + 1) & 2047u;
                }
                if (m) atomicOr(&S.rowflag[i >> 5], 1u << (i & 31));
            }
            __syncthreads();
        }
        if (tid < Ss/TI) {
            unsigned w = S.rowflag[tid >> 1];
            unsigned bits = (w >> ((tid & 1) * 16)) & 0xFFFFu;
            unsigned f = (bits || S.fallback) ? 1u : 0u;
            S.flags[tid] = f;
            if (f) {
                int p = atomicAdd(&g_nwork, 1);
                g_work[p] = (h << 6) | tid;
            }
        }
        __syncthreads();
        for (int t = tid; t < Bb*Ss; t += 256) {
            int b2 = t >> 10, s = t & 1023;
            if (!S.flags[s >> 4]) g_cnt[(b2*Hh + h)*Ss + s] = 0;
        }
    }
    grid_barrier3();

    // ===== Phase B: candidate selection (worklist drain) =====
    {
        SelSmem& S = *reinterpret_cast<SelSmem*>(sm);
        int warp = tid >> 5, lane = tid & 31;
        int nwork = g_nwork;

        for (int w = bid; w < nwork; w += NBLK3) {
            int ht = g_work[w];
            int h = ht >> 6, tile = ht & 63;
            int it0 = tile * TI;
            for (int b = 0; b < Bb; ++b) {
                int bh = b*Hh + h;
                for (int t = tid; t < TI*(Ss/32); t += 256) ((unsigned*)S.uni)[t] = 0u;

                for (int g = 0; g < Gg; ++g) {
                    for (int t = tid; t < Ss; t += 256) {
                        S.hks[t] = g_hk[(bh*Gg + g)*Ss + t];
                        S.sks[t] = g_sk[(h*Gg + g)*Ss + t];
                    }
                    if (tid < TI) {
                        S.myh[tid] = g_hq[(bh*Gg + g)*Ss + it0 + tid];
                        S.mys[tid] = g_sq[(h*Gg + g)*Ss + it0 + tid];
                    }
                    __syncthreads();

                    #pragma unroll
                    for (int iw = 0; iw < 2; ++iw) {
                        int ii = warp*2 + iw;
                        unsigned mh = S.myh[ii], ms = S.mys[ii];
                        int cnt = 0;
                        for (int c = 0; c < Ss/32; ++c) {
                            int j = c*32 + lane;
                            unsigned x = mh ^ S.hks[j];
                            bool m = (((x - 0x01010101u) & ~x & 0x80808080u) != 0u) && (S.sks[j] == ms);
                            unsigned bal = __ballot_sync(0xffffffffu, m);
                            if (lane == 0) S.comb[ii][c] = bal;
                            cnt += __popc(bal);
                        }
                        if (lane == 0) S.cnts[ii] = cnt;
                    }
                    __syncthreads();

                    // rare path: reconstruct group-sim scores from low-rank coeffs
                    for (int ii = 0; ii < TI; ++ii) {
                        if (S.cnts[ii] > KMAX) {
                            if (tid < GDd) {
                                const float* qt = g_qt16 + (bh*Ss + it0 + ii)*Rr;
                                float a = 0.f;
                                #pragma unroll
                                for (int r = 0; r < Rr; ++r)
                                    a += qt[r] * Bq[(h*Rr + r)*DKk + g*GDd + tid];
                                S.qrow[tid] = a;
                            }
                            __syncthreads();
                            if (tid < Rr) {
                                float a = 0.f;
                                #pragma unroll
                                for (int d = 0; d < GDd; ++d)
                                    a += S.qrow[d] * Bk[(h*Rr + tid)*DKk + g*GDd + d];
                                S.qBk[tid] = a;
                            }
                            __syncthreads();
                            for (int j = tid; j < Ss; j += 256) {
                                unsigned key = 0u;
                                if ((S.comb[ii][j >> 5] >> (j & 31)) & 1u) {
                                    const float* kt = g_kt16 + (bh*Ss + j)*Rr;
                                    float sd = 0.f;
                                    #pragma unroll
                                    for (int r = 0; r < Rr; ++r) sd += kt[r]*S.qBk[r];
                                    unsigned u = __float_as_uint(sd);
                                    key = (u & 0x80000000u) ? ~u : (u | 0x80000000u);
                                }
                                S.keys[j] = key;
                            }
                            __syncthreads();
                            unsigned prefix = 0u, himask = 0u;
                            int want = KMAX;
                            for (int pass = 0; pass < 4; ++pass) {
                                int shift = 24 - 8*pass;
                                S.hist[tid] = 0u;
                                __syncthreads();
                                for (int j = tid; j < Ss; j += 256) {
                                    unsigned k2 = S.keys[j];
                                    if ((k2 & himask) == prefix) atomicAdd(&S.hist[(k2 >> shift) & 255], 1u);
                                }
                                __syncthreads();
                                for (int off = 1; off < 256; off <<= 1) {
                                    unsigned add = (tid + off < 256) ? S.hist[tid + off] : 0u;
                                    __syncthreads();
                                    S.hist[tid] += add;
                                    __syncthreads();
                                }
                                unsigned sfx = S.hist[tid];
                                unsigned nxt = (tid < 255) ? S.hist[tid + 1] : 0u;
                                if (sfx >= (unsigned)want && nxt < (unsigned)want) {
                                    S.sDigit = (unsigned)tid;
                                    S.sWant = want - (int)nxt;
                                }
                                __syncthreads();
                                prefix |= S.sDigit << shift;
                                himask |= 0xFFu << shift;
                                want = S.sWant;
                                __syncthreads();
                            }
                            unsigned thresh = prefix;
                            for (int j = tid; j < Ss; j += 256)
                                if (((S.comb[ii][j >> 5] >> (j & 31)) & 1u) && S.keys[j] >= thresh)
                                    atomicOr(&S.uni[ii][j >> 5], 1u << (j & 31));
                            __syncthreads();
                        }
                    }

                    for (int t = tid; t < TI*(Ss/32); t += 256) {
                        int ii = t >> 5, w2 = t & 31;
                        if (S.cnts[ii] <= KMAX) S.uni[ii][w2] |= S.comb[ii][w2];
                    }
                    __syncthreads();
                }

                #pragma unroll
                for (int iw = 0; iw < 2; ++iw) {
                    int ii = warp*2 + iw;
                    unsigned w32 = S.uni[ii][lane];
                    int pc = __popc(w32);
                    int inc = pc;
                    #pragma unroll
                    for (int off = 1; off < 32; off <<= 1) {
                        int v = __shfl_up_sync(0xffffffffu, inc, off);
                        if (lane >= off) inc += v;
                    }
                    int pos = inc - pc;
                    int outBase = (bh*Ss + it0 + ii)*KMAX;
                    unsigned w2 = w32;
                    while (w2 && pos < KMAX) {
                        int bit = __ffs(w2) - 1;
                        w2 &= w2 - 1u;
                        g_cand[outBase + pos] = lane*32 + bit;
                        ++pos;
                    }
                    int tot = __shfl_sync(0xffffffffu, inc, 31);
                    if (lane == 0) g_cnt[bh*Ss + it0 + ii] = min(tot, KMAX);
                }
                __syncthreads();
            }
        }
    }
    grid_barrier3();

    // ===== Phase C: sparse attention + on-demand projections + output GEMM =====
    {
        AttnSmem& S = *reinterpret_cast<AttnSmem*>(sm);
        for (int rr = 0; rr < 16; ++rr) {
            int row = bid*16 + rr;
            int b = row >> 10, i = row & 1023;
            if (tid < Hh) S.cnt8[tid] = g_cnt[(b*Hh + tid)*Ss + i];
            __syncthreads();
            int any = 0;
            #pragma unroll
            for (int h2 = 0; h2 < Hh; ++h2) any |= S.cnt8[h2];
            float* orow = out + row*Dd;
            if (!any) {
                if (tid < 128) ((float4*)orow)[tid] = make_float4(0.f, 0.f, 0.f, 0.f);
                __syncthreads();
                continue;
            }
            for (int h2 = 0; h2 < Hh; ++h2) {
                int cn = S.cnt8[h2];
                if (cn == 0) {
                    if (tid < DKk) S.rowv[h2*DKk + tid] = 0.f;
                    __syncthreads();
                    continue;
                }
                int bh = b*Hh + h2;
                // reconstruct q_up row from low-rank coeffs
                if (tid < DKk) {
                    const float* qt = g_qt16 + (bh*Ss + i)*Rr;
                    float a = 0.f;
                    #pragma unroll
                    for (int r = 0; r < Rr; ++r) a += qt[r]*Bq[(h2*Rr + r)*DKk + tid];
                    S.q64[tid] = a;
                }
                if (tid < cn) S.cj[tid] = g_cand[(bh*Ss + i)*KMAX + tid];
                __syncthreads();
                if (tid < Rr) {
                    float a = 0.f;
                    #pragma unroll
                    for (int d = 0; d < DKk; ++d) a += S.q64[d]*Bk[(h2*Rr + tid)*DKk + d];
                    S.qB[tid] = a;
                }
                __syncthreads();
                float s = -3.4e38f;
                if (tid < cn) {
                    const float* kt = g_kt16 + (bh*Ss + S.cj[tid])*Rr;
                    float acc = 0.f;
                    #pragma unroll
                    for (int r = 0; r < Rr; ++r) acc += kt[r]*S.qB[r];
                    s = acc * 0.125f;
                }
                if (tid < DKk) S.red[tid] = s;
                __syncthreads();
                for (int off = 32; off >= 1; off >>= 1) {
                    if (tid < off) S.red[tid] = fmaxf(S.red[tid], S.red[tid + off]);
                    __syncthreads();
                }
                float mx = S.red[0];
                __syncthreads();
                float e = (tid < cn) ? expf(s - mx) : 0.f;
                if (tid < DKk) S.red[tid] = e;
                __syncthreads();
                for (int off = 32; off >= 1; off >>= 1) {
                    if (tid < off) S.red[tid] += S.red[tid + off];
                    __syncthreads();
                }
                float denom = S.red[0];
                if (tid < DKk) S.pp[tid] = e / denom;
                __syncthreads();
                for (int d = tid; d < Dd; d += 256) {
                    float a = 0.f;
                    for (int c = 0; c < cn; ++c) a += S.pp[c]*value[(b*Ss + S.cj[c])*Dd + d];
                    S.pv[d] = a;
                }
                __syncthreads();
                if (tid < DKk) {
                    float a = 0.f;
                    for (int d = 0; d < Dd; ++d) a += S.pv[d]*Wv[(h2*Dd + d)*DKk + tid];
                    S.rowv[h2*DKk + tid] = a;
                }
                __syncthreads();
            }
            float a0 = 0.f, a1 = 0.f;
            for (int k2 = 0; k2 < Hh*DKk; ++k2) {
                float rv = S.rowv[k2];
                if (rv == 0.f) continue;
                a0 += rv * Wo[k2*Dd + tid];
                a1 += rv * Wo[k2*Dd + tid + 256];
            }
            orow[tid] = a0;
            orow[tid + 256] = a1;
            __syncthreads();
        }
    }
}

// ---------------- launch -----------------------------------------------------------
extern "C" void kernel_launch(void* const* d_in, const int* in_sizes, int n_in,
                              void* d_out, int out_size) {
    const float* query = (const float*)d_in[0];
    const float* key   = (const float*)d_in[1];
    const float* value = (const float*)d_in[2];
    const float* Aq    = (const float*)d_in[3];
    const float* Bq    = (const float*)d_in[4];
    const float* Ak    = (const float*)d_in[5];
    const float* Bk    = (const float*)d_in[6];
    const float* Wv    = (const float*)d_in[7];
    const float* Wo    = (const float*)d_in[8];
    const float* lsh   = (const float*)d_in[9];
    float* out = (float*)d_out;

    k_lowrank_tc<<<dim3(32, KSPLIT, 2), 256>>>(query, key, Aq, Ak);
    k_upproj_hash<<<Bb*Hh*(Ss/16), 256>>>(Bq, Bk, lsh);
    k_tail<<<NBLK3, 256>>>(value, Wv, Wo, Bq, Bk, out);
}